// round 14
// baseline (speedup 1.0000x reference)
#include <cuda_runtime.h>
#include <cuda_bf16.h>
#include <math.h>
#include <stdint.h>

#define NMAX 20000
#define EMAX 500000
#define CDIM 128
#define NPAD (NMAX + 128)

// ---------------------------------------------------------------------------
// Static device scratch
// ---------------------------------------------------------------------------
__device__ float g_h1  [NMAX * CDIM];
__device__ float g_es  [NMAX * 4];
__device__ float g_ed  [NMAX * 4];
__device__ float g_es2p[NMAX * 8];
__device__ float g_ed2p[NMAX * 8];
__device__ float g_tt  [NMAX * 16];
__device__ int   g_cnt   [NMAX];
__device__ int   g_rowptr[NMAX + 1];
__device__ int   g_cursor[NMAX];
__device__ int   g_csrc  [EMAX];
__device__ float g_hsum  [CDIM];
__device__ float g_small [1024];
__device__ float g_logits[256 * CDIM];
__device__ float g_qrow  [256 * 384];
__device__ float g_bn1   [CDIM];
__device__ float g_bn2   [CDIM];
__device__ int   g_sflag;
__device__ int   g_tflag;
__device__ int   g_done;
__device__ float g_Wp  [4 * 512];
__device__ float g_bp  [512];
__device__ float g_fold2[128 * 10];
__device__ __nv_bfloat16 g_A2h[NPAD * 640], g_A2l[NPAD * 640];
__device__ __nv_bfloat16 g_A3h[NPAD * 640], g_A3l[NPAD * 640];
__device__ __nv_bfloat16 g_bt1h[128 * 512], g_bt1l[128 * 512];
__device__ __nv_bfloat16 g_bt2h[5 * 128 * 128], g_bt2l[5 * 128 * 128];
__device__ __nv_bfloat16 g_bt3h[128 * 640], g_bt3l[128 * 640];

// ---------------------------------------------------------------------------
// helpers
// ---------------------------------------------------------------------------
__device__ __forceinline__ uint32_t smem_u32(const void* p) {
    uint32_t a;
    asm("{ .reg .u64 t; cvta.to.shared.u64 t, %1; cvt.u32.u64 %0, t; }" : "=r"(a) : "l"(p));
    return a;
}
__device__ __forceinline__ void ldsm4(uint32_t* r, uint32_t addr) {
    asm volatile("ldmatrix.sync.aligned.m8n8.x4.shared.b16 {%0,%1,%2,%3}, [%4];"
                 : "=r"(r[0]), "=r"(r[1]), "=r"(r[2]), "=r"(r[3]) : "r"(addr));
}
__device__ __forceinline__ void mma16816(float* d, const uint32_t* a, const uint32_t* b) {
    asm volatile(
        "mma.sync.aligned.m16n8k16.row.col.f32.bf16.bf16.f32 "
        "{%0,%1,%2,%3}, {%4,%5,%6,%7}, {%8,%9}, {%0,%1,%2,%3};"
        : "+f"(d[0]), "+f"(d[1]), "+f"(d[2]), "+f"(d[3])
        : "r"(a[0]), "r"(a[1]), "r"(a[2]), "r"(a[3]), "r"(b[0]), "r"(b[1]));
}
__device__ __forceinline__ uint32_t pack_bf(__nv_bfloat16 a, __nv_bfloat16 b) {
    __nv_bfloat162 t;
    t.x = a; t.y = b;
    return *reinterpret_cast<uint32_t*>(&t);
}
#define CPA(dst, src) \
    asm volatile("cp.async.cg.shared.global [%0], [%1], 16;" :: "r"(dst), "l"(src))

// ---------------------------------------------------------------------------
// prep: zero + 3x weight split + drug-linear fold + wfold2 (one launch)
// ---------------------------------------------------------------------------
__global__ void prep_kernel(const float* __restrict__ Wl1, const float* __restrict__ W2,
                            const float* __restrict__ Wl2, const float* __restrict__ Wd,
                            const float* __restrict__ bd,  const float* __restrict__ W1,
                            const float* __restrict__ a2s, const float* __restrict__ a2d,
                            int N, int M1, int M2, int H2,
                            int s0, int s1, int s2, int s3, int s4) {
    int b = blockIdx.x, tid = threadIdx.x;
    if (b < s0) {
        int i = b * 256 + tid;
        if (i < N) g_cnt[i] = 0;
        if (b == 0 && tid < CDIM) { g_hsum[tid] = 0.f; g_bn1[tid] = 0.f; g_bn2[tid] = 0.f; }
        if (b == 0 && tid == 0) { g_sflag = 0; g_tflag = 0; g_done = 0; }
        return;
    }
    b -= s0;
    if (b < s1) {
        int idx = b * 256 + tid;
        if (idx < 128 * M1) {
            int j = idx / M1, k = idx - j * M1;
            float v = Wl1[(size_t)k * 128 + j];
            __nv_bfloat16 h = __float2bfloat16(v);
            g_bt1h[idx] = h;
            g_bt1l[idx] = __float2bfloat16(v - __bfloat162float(h));
        }
        return;
    }
    b -= s1;
    if (b < s2) {
        int idx = b * 256 + tid;
        if (idx < 128 * 128 * H2) {
            int z = idx / 16384, r = idx - z * 16384;
            int j = r / 128, k = r - j * 128;
            float v = W2[(size_t)k * M2 + z * 128 + j];
            __nv_bfloat16 h = __float2bfloat16(v);
            g_bt2h[idx] = h;
            g_bt2l[idx] = __float2bfloat16(v - __bfloat162float(h));
        }
        return;
    }
    b -= s2;
    if (b < s3) {
        int idx = b * 256 + tid;
        if (idx < 128 * M2) {
            int j = idx / M2, k = idx - j * M2;
            float v = Wl2[(size_t)k * 128 + j];
            __nv_bfloat16 h = __float2bfloat16(v);
            g_bt3h[idx] = h;
            g_bt3l[idx] = __float2bfloat16(v - __bfloat162float(h));
        }
        return;
    }
    b -= s3;
    if (b < s4) {
        int j = b * 256 + tid;
        if (j < M1) {
            float a0 = 0.f, a1 = 0.f, a2 = 0.f, a3 = 0.f, ab = 0.f;
#pragma unroll 4
            for (int k = 0; k < CDIM; k++) {
                float w = W1[k * M1 + j];
                a0 += Wd[0 * CDIM + k] * w;
                a1 += Wd[1 * CDIM + k] * w;
                a2 += Wd[2 * CDIM + k] * w;
                a3 += Wd[3 * CDIM + k] * w;
                ab += bd[k] * w;
            }
            g_Wp[0 * M1 + j] = a0;
            g_Wp[1 * M1 + j] = a1;
            g_Wp[2 * M1 + j] = a2;
            g_Wp[3 * M1 + j] = a3;
            g_bp[j] = ab;
        }
        return;
    }
    b -= s4;
    {
        int idx = b * 256 + tid;
        if (idx < CDIM * 2 * H2) {
            int c = idx / (2 * H2), o = idx - c * (2 * H2);
            int h = o % H2;
            const float* av = (o < H2) ? a2s : a2d;
            float s = 0.f;
            for (int k = 0; k < CDIM; k++) s += W2[c * M2 + h * CDIM + k] * av[h * CDIM + k];
            g_fold2[c * (2 * H2) + o] = s;
        }
    }
}

// ---------------------------------------------------------------------------
// combined: edge count (8 edges/thread) + layer-1 logits + q-precompute
// ---------------------------------------------------------------------------
__global__ void cnt_es1_q_kernel(const int* __restrict__ ei, int E,
                                 const int* __restrict__ trip,
                                 const float* __restrict__ a1s,
                                 const float* __restrict__ a1d, int N, int M1,
                                 const float* __restrict__ cell,
                                 const float* __restrict__ Wc, const float* __restrict__ bc,
                                 const float* __restrict__ Wq, const float* __restrict__ bq,
                                 int CF,
                                 int c0, int c1) {
    __shared__ float sm[1024];
    __shared__ float crow[128];
    int b = blockIdx.x, tid = threadIdx.x;
    if (b < c0) {                       // count (8 edges/thread)
        int e0 = (b * 256 + tid) * 8;
#pragma unroll
        for (int j = 0; j < 8; j += 2) {
            int e = e0 + j;
            if (e + 1 < E) {
                int2 s = *(const int2*)(ei + e);
                int2 d = *(const int2*)(ei + E + e);
                if (s.x != d.x) atomicAdd(&g_cnt[d.x], 1);
                if (s.y != d.y) atomicAdd(&g_cnt[d.y], 1);
            } else if (e < E) {
                int s = ei[e], d = ei[E + e];
                if (s != d) atomicAdd(&g_cnt[d], 1);
            }
        }
        return;
    }
    b -= c0;
    if (b < c1) {                       // es1
        float* f1 = sm;
        if (tid < 16) {
            int h = tid >> 2, i = tid & 3;
            float s = 0.f;
            for (int k = 0; k < CDIM; k++) s += g_Wp[i * M1 + h * CDIM + k] * a1s[h * CDIM + k];
            f1[tid] = s;
        } else if (tid < 32) {
            int t = tid - 16;
            int h = t >> 2, i = t & 3;
            float s = 0.f;
            for (int k = 0; k < CDIM; k++) s += g_Wp[i * M1 + h * CDIM + k] * a1d[h * CDIM + k];
            f1[tid] = s;
        } else if (tid < 36) {
            int h = tid - 32;
            float s = 0.f;
            for (int k = 0; k < CDIM; k++) s += g_bp[h * CDIM + k] * a1s[h * CDIM + k];
            f1[tid] = s;
        } else if (tid < 40) {
            int h = tid - 36;
            float s = 0.f;
            for (int k = 0; k < CDIM; k++) s += g_bp[h * CDIM + k] * a1d[h * CDIM + k];
            f1[tid] = s;
        }
        __syncthreads();
        int n = b * 256 + tid;
        if (n >= N) return;
        int4 tv = *(const int4*)(trip + n * 4);
        float t0 = (float)tv.x, t1 = (float)tv.y, t2 = (float)tv.z, t3 = (float)tv.w;
        float4 es, ed;
        float* esp = &es.x;
        float* edp = &ed.x;
#pragma unroll
        for (int h = 0; h < 4; h++) {
            esp[h] = f1[32 + h] + t0 * f1[h * 4 + 0] + t1 * f1[h * 4 + 1]
                   + t2 * f1[h * 4 + 2] + t3 * f1[h * 4 + 3];
            edp[h] = f1[36 + h] + t0 * f1[16 + h * 4 + 0] + t1 * f1[16 + h * 4 + 1]
                   + t2 * f1[16 + h * 4 + 2] + t3 * f1[16 + h * 4 + 3];
        }
        *(float4*)(g_es + n * 4) = es;
        *(float4*)(g_ed + n * 4) = ed;
        return;
    }
    b -= c1;
    {                                   // q precompute for batch row b
        for (int i = tid; i < CF; i += 256) sm[i] = cell[(size_t)b * CF + i];
        __syncthreads();
        if (tid < 128) {
            float a = bc[tid];
            for (int k = 0; k < CF; k++) a += sm[k] * Wc[k * 128 + tid];
            crow[tid] = a > 0.f ? a : 0.f;
        }
        __syncthreads();
        for (int mI = tid; mI < 384; mI += 256) {
            float q = bq[mI];
            for (int k = 0; k < 128; k++) q += crow[k] * Wq[k * 384 + mI];
            g_qrow[b * 384 + mI] = q > 0.f ? q : 0.f;
        }
    }
}

// ---------------------------------------------------------------------------
// fused scan + fill: block 0 scans (sets flag), others spin then fill
// (8 edges/thread). All blocks resident -> spin is deadlock-free.
// ---------------------------------------------------------------------------
__global__ void __launch_bounds__(256)
scan_fill_kernel(const int* __restrict__ ei, int E, int N) {
    int tid = threadIdx.x;
    if (blockIdx.x == 0) {
        __shared__ int wsum[8];
        __shared__ int carry_s;
        int lane = tid & 31, wid = tid >> 5;
        if (tid == 0) { carry_s = 0; g_rowptr[0] = 0; }
        __syncthreads();
        int NT = (N + 3) >> 2;
        for (int base = 0; base < NT; base += 256) {
            int i4 = base + tid;
            int b0 = i4 * 4;
            int4 v = make_int4(0, 0, 0, 0);
            if (b0 + 3 < N) {
                v = *(const int4*)(g_cnt + b0);
            } else if (b0 < N) {
                v.x = g_cnt[b0];
                if (b0 + 1 < N) v.y = g_cnt[b0 + 1];
                if (b0 + 2 < N) v.z = g_cnt[b0 + 2];
            }
            int p1 = v.x, p2 = p1 + v.y, p3 = p2 + v.z, p4 = p3 + v.w;
            int x = p4;
#pragma unroll
            for (int o = 1; o < 32; o <<= 1) {
                int t = __shfl_up_sync(0xffffffffu, x, o);
                if (lane >= o) x += t;
            }
            if (lane == 31) wsum[wid] = x;
            __syncthreads();
            if (wid == 0) {
                int s = (lane < 8) ? wsum[lane] : 0;
#pragma unroll
                for (int o = 1; o < 8; o <<= 1) {
                    int t = __shfl_up_sync(0xffffffffu, s, o);
                    if (lane >= o) s += t;
                }
                if (lane < 8) wsum[lane] = s;
            }
            __syncthreads();
            int pre = carry_s + (wid ? wsum[wid - 1] : 0) + (x - p4);
            if (b0 < N)     { g_rowptr[b0 + 1] = pre + p1; g_cursor[b0]     = pre; }
            if (b0 + 1 < N) { g_rowptr[b0 + 2] = pre + p2; g_cursor[b0 + 1] = pre + p1; }
            if (b0 + 2 < N) { g_rowptr[b0 + 3] = pre + p3; g_cursor[b0 + 2] = pre + p2; }
            if (b0 + 3 < N) { g_rowptr[b0 + 4] = pre + p4; g_cursor[b0 + 3] = pre + p3; }
            __syncthreads();
            if (tid == 0) carry_s += wsum[7];
            __syncthreads();
        }
        __threadfence();
        if (tid == 0) atomicExch(&g_sflag, 1);
        return;
    }
    // fill blocks: spin until scan done
    if (tid == 0) {
        while (atomicAdd(&g_sflag, 0) == 0) __nanosleep(64);
    }
    __syncthreads();
    int e0 = ((blockIdx.x - 1) * 256 + tid) * 8;
#pragma unroll
    for (int j = 0; j < 8; j += 2) {
        int e = e0 + j;
        if (e + 1 < E) {
            int2 s = *(const int2*)(ei + e);
            int2 d = *(const int2*)(ei + E + e);
            if (s.x != d.x) { int p = atomicAdd(&g_cursor[d.x], 1); g_csrc[p] = s.x; }
            if (s.y != d.y) { int p = atomicAdd(&g_cursor[d.y], 1); g_csrc[p] = s.y; }
        } else if (e < E) {
            int s = ei[e], d = ei[E + e];
            if (s != d) { int p = atomicAdd(&g_cursor[d], 1); g_csrc[p] = s; }
        }
    }
}

// ---------------------------------------------------------------------------
// Layer-1 aggregation
// ---------------------------------------------------------------------------
__global__ void agg_rank4_kernel(const int* __restrict__ trip, int N) {
    const int H = 4;
    int warp = (blockIdx.x * blockDim.x + threadIdx.x) >> 5;
    int lane = threadIdx.x & 31;
    if (warp >= N) return;
    int n   = warp;
    int r0  = g_rowptr[n];
    int deg = g_rowptr[n + 1] - r0;
    int tot = deg + 1;

    float4 edv4 = *(const float4*)(g_ed + n * 4);
    float edv[H] = {edv4.x, edv4.y, edv4.z, edv4.w};
    float m[H] = {-1e30f, -1e30f, -1e30f, -1e30f};
    for (int i = lane; i < tot; i += 32) {
        int src = (i < deg) ? g_csrc[r0 + i] : n;
        float4 es = *(const float4*)(g_es + src * 4);
        float ev[H] = {es.x, es.y, es.z, es.w};
#pragma unroll
        for (int h = 0; h < H; h++) {
            float e = ev[h] + edv[h];
            e = e > 0.f ? e : 0.2f * e;
            m[h] = fmaxf(m[h], e);
        }
    }
#pragma unroll
    for (int h = 0; h < H; h++)
        for (int o = 16; o; o >>= 1) m[h] = fmaxf(m[h], __shfl_xor_sync(0xffffffffu, m[h], o));
    float4 acc[H];
    float z[H];
#pragma unroll
    for (int h = 0; h < H; h++) { acc[h] = make_float4(0.f, 0.f, 0.f, 0.f); z[h] = 0.f; }
    for (int i = lane; i < tot; i += 32) {
        int src = (i < deg) ? g_csrc[r0 + i] : n;
        float4 es = *(const float4*)(g_es + src * 4);
        float ev[H] = {es.x, es.y, es.z, es.w};
        int4 tv = *(const int4*)(trip + src * 4);
        float4 tf = make_float4((float)tv.x, (float)tv.y, (float)tv.z, (float)tv.w);
#pragma unroll
        for (int h = 0; h < H; h++) {
            float e = ev[h] + edv[h];
            e = e > 0.f ? e : 0.2f * e;
            float w = __expf(e - m[h]);
            z[h] += w;
            acc[h].x += w * tf.x; acc[h].y += w * tf.y;
            acc[h].z += w * tf.z; acc[h].w += w * tf.w;
        }
    }
#pragma unroll
    for (int h = 0; h < H; h++) {
        for (int o = 16; o; o >>= 1) {
            acc[h].x += __shfl_xor_sync(0xffffffffu, acc[h].x, o);
            acc[h].y += __shfl_xor_sync(0xffffffffu, acc[h].y, o);
            acc[h].z += __shfl_xor_sync(0xffffffffu, acc[h].z, o);
            acc[h].w += __shfl_xor_sync(0xffffffffu, acc[h].w, o);
            z[h]     += __shfl_xor_sync(0xffffffffu, z[h], o);
        }
    }
    if (lane == 0) {
#pragma unroll
        for (int h = 0; h < H; h++) {
            float iz = 1.f / z[h];
            float4 r = make_float4(acc[h].x * iz, acc[h].y * iz, acc[h].z * iz, acc[h].w * iz);
            *(float4*)(g_tt + n * 16 + h * 4) = r;
        }
    }
}

// ---------------------------------------------------------------------------
// tgemm_r4: 64-row tile, 2-stage, 3 CTA/SM, colsum epilogue
// ---------------------------------------------------------------------------
__global__ void __launch_bounds__(256, 3)
tgemm_r4(const float* __restrict__ b1,
         const __nv_bfloat16* __restrict__ Bh, const __nv_bfloat16* __restrict__ Bl,
         float* __restrict__ Cf, int M, const float* __restrict__ cbias) {
    const int K = 512;
    extern __shared__ __align__(16) char dsm[];
    char*    sAc = dsm;
    uint32_t sAu = smem_u32(dsm);
    uint32_t sBu = sAu + 16384;

    int tid  = threadIdx.x;
    int wid  = tid >> 5;
    int lane = tid & 31;
    int m0   = blockIdx.y * 64;
    int wm   = wid & 1;
    int wn   = wid >> 1;

    float acc[2][4][4];
#pragma unroll
    for (int i = 0; i < 2; i++)
#pragma unroll
        for (int j = 0; j < 4; j++)
#pragma unroll
            for (int l = 0; l < 4; l++) acc[i][j][l] = 0.f;

#define STAGEB(BUF, KC)                                                        \
    {                                                                          \
        int _kc = (KC);                                                        \
        _Pragma("unroll")                                                      \
        for (int it = 0; it < 4; it++) {                                       \
            int idx = it * 256 + tid;                                          \
            int row = idx >> 3, ch = idx & 7;                                  \
            const __nv_bfloat16* gs = ((ch < 4) ? Bh : Bl)                     \
                + (size_t)row * K + _kc + (ch & 3) * 8;                        \
            uint32_t dst = sBu + (BUF) * 16384 + row * 128                     \
                + ((ch ^ (row & 7)) << 4);                                     \
            CPA(dst, gs);                                                      \
        }                                                                      \
    }

#define STAGEA(BUF, KC)                                                        \
    {                                                                          \
        int _kc = (KC);                                                        \
        int _h  = _kc >> 7;                                                    \
        _Pragma("unroll")                                                      \
        for (int it = 0; it < 2; it++) {                                       \
            int idx = it * 256 + tid;                                          \
            int row = idx >> 3, cg = idx & 7;                                  \
            int gr = m0 + row; if (gr >= M) gr = M - 1;                        \
            float4 t = *(const float4*)(g_tt + gr * 16 + _h * 4);              \
            int j = _kc + cg * 4;                                              \
            float4 w0 = *(const float4*)(g_Wp + 0 * 512 + j);                  \
            float4 w1 = *(const float4*)(g_Wp + 1 * 512 + j);                  \
            float4 w2 = *(const float4*)(g_Wp + 2 * 512 + j);                  \
            float4 w3 = *(const float4*)(g_Wp + 3 * 512 + j);                  \
            float4 bb = *(const float4*)(g_bp + j);                            \
            float4 b2v = *(const float4*)(b1 + j);                             \
            float v0 = bb.x + b2v.x + t.x * w0.x + t.y * w1.x + t.z * w2.x + t.w * w3.x; \
            float v1 = bb.y + b2v.y + t.x * w0.y + t.y * w1.y + t.z * w2.y + t.w * w3.y; \
            float v2 = bb.z + b2v.z + t.x * w0.z + t.y * w1.z + t.z * w2.z + t.w * w3.z; \
            float v3 = bb.w + b2v.w + t.x * w0.w + t.y * w1.w + t.z * w2.w + t.w * w3.w; \
            v0 = v0 > 0.f ? v0 : __expf(v0) - 1.f;                             \
            v1 = v1 > 0.f ? v1 : __expf(v1) - 1.f;                             \
            v2 = v2 > 0.f ? v2 : __expf(v2) - 1.f;                             \
            v3 = v3 > 0.f ? v3 : __expf(v3) - 1.f;                             \
            __nv_bfloat16 h0 = __float2bfloat16(v0);                           \
            __nv_bfloat16 h1 = __float2bfloat16(v1);                           \
            __nv_bfloat16 h2 = __float2bfloat16(v2);                           \
            __nv_bfloat16 h3 = __float2bfloat16(v3);                           \
            uint2 hi2 = make_uint2(pack_bf(h0, h1), pack_bf(h2, h3));          \
            uint2 lo2 = make_uint2(                                            \
                pack_bf(__float2bfloat16(v0 - __bfloat162float(h0)),           \
                        __float2bfloat16(v1 - __bfloat162float(h1))),          \
                pack_bf(__float2bfloat16(v2 - __bfloat162float(h2)),           \
                        __float2bfloat16(v3 - __bfloat162float(h3))));         \
            int ch = cg >> 1, rem = (cg & 1) * 8;                              \
            char* base = sAc + (BUF) * 8192 + row * 128;                       \
            *(uint2*)(base + (((ch)     ^ (row & 7)) << 4) + rem) = hi2;       \
            *(uint2*)(base + (((ch + 4) ^ (row & 7)) << 4) + rem) = lo2;       \
        }                                                                      \
    }

    int nk = K >> 5;
    STAGEB(0, 0)
    asm volatile("cp.async.commit_group;");
    STAGEA(0, 0)

    for (int i = 0; i < nk; i++) {
        int buf = i & 1;
        if (i + 1 < nk) {
            STAGEB(buf ^ 1, (i + 1) * 32)
            asm volatile("cp.async.commit_group;");
            STAGEA(buf ^ 1, (i + 1) * 32)
            asm volatile("cp.async.wait_group 1;");
        } else {
            asm volatile("cp.async.wait_group 0;");
        }
        __syncthreads();

        uint32_t a_base = sAu + buf * 8192;
        uint32_t b_base = sBu + buf * 16384;
#pragma unroll
        for (int ks = 0; ks < 2; ks++) {
            uint32_t ah[2][4], al[2][4], bh[2][4], bl[2][4];
            int arow = (lane & 7) + ((lane >> 3) & 1) * 8;
            int akg  = 2 * ks + (lane >> 4);
#pragma unroll
            for (int mf = 0; mf < 2; mf++) {
                int r = 32 * wm + 16 * mf + arow;
                ldsm4(ah[mf], a_base + r * 128 + (((akg)     ^ (r & 7)) << 4));
                ldsm4(al[mf], a_base + r * 128 + (((akg + 4) ^ (r & 7)) << 4));
            }
            int brow = (lane & 7) + (lane >> 4) * 8;
            int bkg  = 2 * ks + ((lane >> 3) & 1);
#pragma unroll
            for (int q = 0; q < 2; q++) {
                int r = 32 * wn + 16 * q + brow;
                ldsm4(bh[q], b_base + r * 128 + (((bkg)     ^ (r & 7)) << 4));
                ldsm4(bl[q], b_base + r * 128 + (((bkg + 4) ^ (r & 7)) << 4));
            }
#pragma unroll
            for (int mf = 0; mf < 2; mf++) {
#pragma unroll
                for (int q = 0; q < 2; q++) {
                    mma16816(acc[mf][2 * q + 0], ah[mf], &bh[q][0]);
                    mma16816(acc[mf][2 * q + 1], ah[mf], &bh[q][2]);
                    mma16816(acc[mf][2 * q + 0], al[mf], &bh[q][0]);
                    mma16816(acc[mf][2 * q + 1], al[mf], &bh[q][2]);
                    mma16816(acc[mf][2 * q + 0], ah[mf], &bl[q][0]);
                    mma16816(acc[mf][2 * q + 1], ah[mf], &bl[q][2]);
                }
            }
        }
        __syncthreads();
    }
#undef STAGEA
#undef STAGEB

    float* colsum = (float*)dsm;
    if (tid < 128) colsum[tid] = 0.f;
    __syncthreads();
#pragma unroll
    for (int mf = 0; mf < 2; mf++) {
        int r0 = m0 + 32 * wm + 16 * mf + (lane >> 2);
#pragma unroll
        for (int nf = 0; nf < 4; nf++) {
            int col = 32 * wn + 8 * nf + 2 * (lane & 3);
            float cb0 = cbias[col], cb1 = cbias[col + 1];
            float s0 = 0.f, s1 = 0.f;
#pragma unroll
            for (int rr = 0; rr < 2; rr++) {
                int r = r0 + rr * 8;
                if (r >= M) continue;
                float v0 = acc[mf][nf][2 * rr + 0] + cb0;
                float v1 = acc[mf][nf][2 * rr + 1] + cb1;
                *(float2*)(Cf + (size_t)r * CDIM + col) = make_float2(v0, v1);
                s0 += v0; s1 += v1;
            }
            atomicAdd(&colsum[col], s0);
            atomicAdd(&colsum[col + 1], s1);
        }
    }
    __syncthreads();
    if (tid < 128) atomicAdd(&g_hsum[tid], colsum[tid]);
}

// ---------------------------------------------------------------------------
// generic tgemm: 64-row tile, 2-stage, 3 CTA/SM
// ---------------------------------------------------------------------------
__global__ void __launch_bounds__(256, 3)
tgemm(const __nv_bfloat16* __restrict__ Ah, const __nv_bfloat16* __restrict__ Al,
      int lda, int boa,
      const __nv_bfloat16* __restrict__ Bh, const __nv_bfloat16* __restrict__ Bl, int bob,
      float* __restrict__ Cf, __nv_bfloat16* __restrict__ Ch, __nv_bfloat16* __restrict__ Cl,
      int ldc, int boc,
      int M, int K, const float* __restrict__ cbias, int bocb, int celu) {
    Ah += (size_t)blockIdx.z * boa;
    Al += (size_t)blockIdx.z * boa;
    Bh += (size_t)blockIdx.z * bob;
    Bl += (size_t)blockIdx.z * bob;
    if (Cf) Cf += (size_t)blockIdx.z * boc;
    if (Ch) { Ch += (size_t)blockIdx.z * boc; Cl += (size_t)blockIdx.z * boc; }
    cbias += (size_t)blockIdx.z * bocb;
    int sum_only = (Cf == nullptr) && (Ch == nullptr);

    extern __shared__ __align__(16) char dsm[];
    uint32_t sAu = smem_u32(dsm);
    uint32_t sBu = sAu + 16384;

    int tid  = threadIdx.x;
    int wid  = tid >> 5;
    int lane = tid & 31;
    int m0   = blockIdx.y * 64;
    int wm   = wid & 1;
    int wn   = wid >> 1;

    float acc[2][4][4];
#pragma unroll
    for (int i = 0; i < 2; i++)
#pragma unroll
        for (int j = 0; j < 4; j++)
#pragma unroll
            for (int l = 0; l < 4; l++) acc[i][j][l] = 0.f;

#define STAGE(BUF, KC)                                                         \
    {                                                                          \
        int _kc = (KC);                                                        \
        _Pragma("unroll")                                                      \
        for (int it = 0; it < 2; it++) {                                       \
            int idx = it * 256 + tid;                                          \
            int row = idx >> 3, ch = idx & 7;                                  \
            const __nv_bfloat16* gs = ((ch < 4) ? Ah : Al)                     \
                + (size_t)(m0 + row) * lda + _kc + (ch & 3) * 8;               \
            uint32_t dst = sAu + (BUF) * 8192 + row * 128                      \
                + ((ch ^ (row & 7)) << 4);                                     \
            CPA(dst, gs);                                                      \
        }                                                                      \
        _Pragma("unroll")                                                      \
        for (int it = 0; it < 4; it++) {                                       \
            int idx = it * 256 + tid;                                          \
            int row = idx >> 3, ch = idx & 7;                                  \
            const __nv_bfloat16* gs = ((ch < 4) ? Bh : Bl)                     \
                + (size_t)row * K + _kc + (ch & 3) * 8;                        \
            uint32_t dst = sBu + (BUF) * 16384 + row * 128                     \
                + ((ch ^ (row & 7)) << 4);                                     \
            CPA(dst, gs);                                                      \
        }                                                                      \
    }

    int nk = K >> 5;
    STAGE(0, 0)
    asm volatile("cp.async.commit_group;");

    for (int i = 0; i < nk; i++) {
        int buf = i & 1;
        if (i + 1 < nk) {
            STAGE(buf ^ 1, (i + 1) * 32)
            asm volatile("cp.async.commit_group;");
            asm volatile("cp.async.wait_group 1;");
        } else {
            asm volatile("cp.async.wait_group 0;");
        }
        __syncthreads();

        uint32_t a_base = sAu + buf * 8192;
        uint32_t b_base = sBu + buf * 16384;
#pragma unroll
        for (int ks = 0; ks < 2; ks++) {
            uint32_t ah[2][4], al[2][4], bh[2][4], bl[2][4];
            int arow = (lane & 7) + ((lane >> 3) & 1) * 8;
            int akg  = 2 * ks + (lane >> 4);
#pragma unroll
            for (int mf = 0; mf < 2; mf++) {
                int r = 32 * wm + 16 * mf + arow;
                ldsm4(ah[mf], a_base + r * 128 + (((akg)     ^ (r & 7)) << 4));
                ldsm4(al[mf], a_base + r * 128 + (((akg + 4) ^ (r & 7)) << 4));
            }
            int brow = (lane & 7) + (lane >> 4) * 8;
            int bkg  = 2 * ks + ((lane >> 3) & 1);
#pragma unroll
            for (int q = 0; q < 2; q++) {
                int r = 32 * wn + 16 * q + brow;
                ldsm4(bh[q], b_base + r * 128 + (((bkg)     ^ (r & 7)) << 4));
                ldsm4(bl[q], b_base + r * 128 + (((bkg + 4) ^ (r & 7)) << 4));
            }
#pragma unroll
            for (int mf = 0; mf < 2; mf++) {
#pragma unroll
                for (int q = 0; q < 2; q++) {
                    mma16816(acc[mf][2 * q + 0], ah[mf], &bh[q][0]);
                    mma16816(acc[mf][2 * q + 1], ah[mf], &bh[q][2]);
                    mma16816(acc[mf][2 * q + 0], al[mf], &bh[q][0]);
                    mma16816(acc[mf][2 * q + 1], al[mf], &bh[q][2]);
                    mma16816(acc[mf][2 * q + 0], ah[mf], &bl[q][0]);
                    mma16816(acc[mf][2 * q + 1], ah[mf], &bl[q][2]);
                }
            }
        }
        __syncthreads();
    }
#undef STAGE

    float* colsum = (float*)dsm;
    if (sum_only) {
        if (tid < 128) colsum[tid] = 0.f;
        __syncthreads();
    }
#pragma unroll
    for (int mf = 0; mf < 2; mf++) {
        int r0 = m0 + 32 * wm + 16 * mf + (lane >> 2);
#pragma unroll
        for (int nf = 0; nf < 4; nf++) {
            int col = 32 * wn + 8 * nf + 2 * (lane & 3);
            float cb0 = cbias[col], cb1 = cbias[col + 1];
            float s0 = 0.f, s1 = 0.f;
#pragma unroll
            for (int rr = 0; rr < 2; rr++) {
                int r = r0 + rr * 8;
                if (r >= M) continue;
                float v0 = acc[mf][nf][2 * rr + 0] + cb0;
                float v1 = acc[mf][nf][2 * rr + 1] + cb1;
                if (Cf) {
                    *(float2*)(Cf + (size_t)r * ldc + col) = make_float2(v0, v1);
                } else if (Ch) {
                    if (celu) {
                        v0 = v0 > 0.f ? v0 : __expf(v0) - 1.f;
                        v1 = v1 > 0.f ? v1 : __expf(v1) - 1.f;
                    }
                    __nv_bfloat16 h0 = __float2bfloat16(v0);
                    __nv_bfloat16 h1 = __float2bfloat16(v1);
                    size_t o = (size_t)r * ldc + col;
                    *(uint32_t*)(Ch + o) = pack_bf(h0, h1);
                    *(uint32_t*)(Cl + o) =
                        pack_bf(__float2bfloat16(v0 - __bfloat162float(h0)),
                                __float2bfloat16(v1 - __bfloat162float(h1)));
                } else {
                    s0 += v0; s1 += v1;
                }
            }
            if (sum_only) {
                atomicAdd(&colsum[col], s0);
                atomicAdd(&colsum[col + 1], s1);
            }
        }
    }
    if (sum_only) {
        __syncthreads();
        if (tid < 128) atomicAdd(&g_hsum[tid], colsum[tid]);
    }
}

// ---------------------------------------------------------------------------
// es2
// ---------------------------------------------------------------------------
__global__ void es2_kernel(int N, int H) {
    __shared__ float wt[CDIM * 10];
    int tid = threadIdx.x;
    int TW = CDIM * 2 * H;
    for (int i = tid; i < TW; i += blockDim.x) wt[i] = g_fold2[i];
    __syncthreads();
    int warp = blockIdx.x * (blockDim.x >> 5) + (tid >> 5);
    int lane = tid & 31;
    if (warp >= N) return;
    float4 hv = *(const float4*)(g_h1 + (size_t)warp * CDIM + lane * 4);
    float s[10];
#pragma unroll
    for (int o = 0; o < 10; o++) s[o] = 0.f;
    float hvv[4] = {hv.x, hv.y, hv.z, hv.w};
#pragma unroll
    for (int j = 0; j < 4; j++) {
        int c = lane * 4 + j;
        for (int o = 0; o < 2 * H; o++) s[o] += hvv[j] * wt[c * (2 * H) + o];
    }
    for (int o = 0; o < 2 * H; o++)
        for (int off = 16; off; off >>= 1) s[o] += __shfl_xor_sync(0xffffffffu, s[o], off);
    if (lane < H)          g_es2p[warp * 8 + lane] = s[lane];
    else if (lane < 2 * H) g_ed2p[warp * 8 + lane - H] = s[lane];
}

// ---------------------------------------------------------------------------
// Layer-2 aggregation
// ---------------------------------------------------------------------------
__global__ void agg2_kernel(const float* __restrict__ feat, int N) {
    const int H = 5;
    int warp = (blockIdx.x * blockDim.x + threadIdx.x) >> 5;
    int lane = threadIdx.x & 31;
    if (warp >= N) return;
    int n   = warp;
    int r0  = g_rowptr[n];
    int deg = g_rowptr[n + 1] - r0;
    int tot = deg + 1;

    float edv[H], m[H];
    {
        float4 e4 = *(const float4*)(g_ed2p + n * 8);
        edv[0] = e4.x; edv[1] = e4.y; edv[2] = e4.z; edv[3] = e4.w;
        edv[4] = g_ed2p[n * 8 + 4];
    }
#pragma unroll
    for (int h = 0; h < H; h++) m[h] = -1e30f;
    for (int i = lane; i < tot; i += 32) {
        int src = (i < deg) ? g_csrc[r0 + i] : n;
        float4 e4 = *(const float4*)(g_es2p + src * 8);
        float ev[H] = {e4.x, e4.y, e4.z, e4.w, g_es2p[src * 8 + 4]};
#pragma unroll
        for (int h = 0; h < H; h++) {
            float e = ev[h] + edv[h];
            e = e > 0.f ? e : 0.2f * e;
            m[h] = fmaxf(m[h], e);
        }
    }
#pragma unroll
    for (int h = 0; h < H; h++)
        for (int o = 16; o; o >>= 1) m[h] = fmaxf(m[h], __shfl_xor_sync(0xffffffffu, m[h], o));

    float4 acc[H];
    float zp[H];
#pragma unroll
    for (int h = 0; h < H; h++) { acc[h] = make_float4(0.f, 0.f, 0.f, 0.f); zp[h] = 0.f; }

    for (int t = 0; t < tot; t += 32) {
        int i = t + lane;
        int src = n;
        float w[H];
        if (i < tot) {
            src = (i < deg) ? g_csrc[r0 + i] : n;
            float4 e4 = *(const float4*)(g_es2p + src * 8);
            float ev[H] = {e4.x, e4.y, e4.z, e4.w, g_es2p[src * 8 + 4]};
#pragma unroll
            for (int h = 0; h < H; h++) {
                float e = ev[h] + edv[h];
                e = e > 0.f ? e : 0.2f * e;
                w[h] = __expf(e - m[h]);
                zp[h] += w[h];
            }
        } else {
#pragma unroll
            for (int h = 0; h < H; h++) w[h] = 0.f;
        }
        int cnt = tot - t;
        if (cnt > 32) cnt = 32;
#pragma unroll 4
        for (int j = 0; j < cnt; j++) {
            int s = __shfl_sync(0xffffffffu, src, j);
            float wj[H];
#pragma unroll
            for (int h = 0; h < H; h++) wj[h] = __shfl_sync(0xffffffffu, w[h], j);
            float4 v = *(const float4*)(feat + (size_t)s * CDIM + lane * 4);
#pragma unroll
            for (int h = 0; h < H; h++) {
                acc[h].x += wj[h] * v.x; acc[h].y += wj[h] * v.y;
                acc[h].z += wj[h] * v.z; acc[h].w += wj[h] * v.w;
            }
        }
    }
#pragma unroll
    for (int h = 0; h < H; h++)
        for (int o = 16; o; o >>= 1) zp[h] += __shfl_xor_sync(0xffffffffu, zp[h], o);

#pragma unroll
    for (int h = 0; h < H; h++) {
        float iz = 1.f / zp[h];
        float ax = acc[h].x * iz, ay = acc[h].y * iz;
        float az = acc[h].z * iz, aw = acc[h].w * iz;
        __nv_bfloat16 hx = __float2bfloat16(ax);
        __nv_bfloat16 hy = __float2bfloat16(ay);
        __nv_bfloat16 hz = __float2bfloat16(az);
        __nv_bfloat16 hw = __float2bfloat16(aw);
        size_t o = (size_t)n * (H * CDIM) + h * CDIM + lane * 4;
        *(uint2*)(g_A2h + o) = make_uint2(pack_bf(hx, hy), pack_bf(hz, hw));
        *(uint2*)(g_A2l + o) = make_uint2(
            pack_bf(__float2bfloat16(ax - __bfloat162float(hx)),
                    __float2bfloat16(ay - __bfloat162float(hy))),
            pack_bf(__float2bfloat16(az - __bfloat162float(hz)),
                    __float2bfloat16(aw - __bfloat162float(hw))));
    }
}

// ---------------------------------------------------------------------------
// fused tail: block 0 = tail0 (sets flag); blocks 1..B = tail1 rows (spin);
// last tail1 block performs the BN normalize. 257 blocks all resident.
// ---------------------------------------------------------------------------
__global__ void __launch_bounds__(384)
tail_all_kernel(const float* __restrict__ Wfc, const float* __restrict__ bfc,
                const float* __restrict__ Whg, const float* __restrict__ bhg,
                const float* __restrict__ Wv,  const float* __restrict__ bv,
                const float* __restrict__ h_mat, const float* __restrict__ h_bias,
                const float* __restrict__ gamma, const float* __restrict__ beta,
                float* __restrict__ out, int N, int B, int HOUT) {
    int tid = threadIdx.x;
    if (blockIdx.x == 0) {
        __shared__ float h[128];
        __shared__ float tm[256];
        __shared__ float hg[128];
        if (tid < 128) h[tid] = g_hsum[tid] / (float)N;
        __syncthreads();
        if (tid < 256) {
            float a = bfc[tid];
            for (int i = 0; i < 128; i++) a += h[i] * Wfc[i * 256 + tid];
            tm[tid] = a > 0.f ? a : 0.f;
        }
        __syncthreads();
        if (tid < 128) {
            float a = bhg[tid];
            for (int i = 0; i < 256; i++) a += tm[i] * Whg[i * 128 + tid];
            hg[tid] = a;
        }
        __syncthreads();
        if (tid < 384) {
            float a = bv[tid];
            for (int i = 0; i < 128; i++) a += hg[i] * Wv[i * 384 + tid];
            g_small[tid] = a > 0.f ? a : 0.f;
            float hs = 0.f;
            for (int hh = 0; hh < HOUT; hh++) hs += h_mat[hh * 384 + tid];
            g_small[384 + tid] = hs;
        }
        if (tid == 0) {
            float hb = 0.f;
            for (int i = 0; i < HOUT; i++) hb += h_bias[i];
            g_small[768] = hb;
        }
        __syncthreads();
        __threadfence();
        if (tid == 0) atomicExch(&g_tflag, 1);
        return;
    }
    // tail1 blocks: wait for tail0
    if (tid == 0) {
        while (atomicAdd(&g_tflag, 0) == 0) __nanosleep(64);
    }
    __syncthreads();
    int b = blockIdx.x - 1;
    __shared__ float red[128];
    __shared__ int isLast;
    if (tid < 128) {
        float part = 0.f;
        for (int mI = tid; mI < 384; mI += 128)
            part += g_small[384 + mI] * g_small[mI] * g_qrow[b * 384 + mI];
        red[tid] = part;
    }
    __syncthreads();
    for (int o = 64; o; o >>= 1) {
        if (tid < o) red[tid] += red[tid + o];
        __syncthreads();
    }
    float att = red[0] + g_small[768];
    if (tid < 128) {
        float l = 0.f;
#pragma unroll
        for (int j = 0; j < 3; j++) {
            int k = tid * 3 + j;
            l += g_small[k] * g_qrow[b * 384 + k];
        }
        float v = att * l;
        g_logits[b * 128 + tid] = v;
        atomicAdd(&g_bn1[tid], v);
        atomicAdd(&g_bn2[tid], v * v);
    }
    __threadfence();
    __syncthreads();
    if (tid == 0) isLast = (atomicAdd(&g_done, 1) == B - 1) ? 1 : 0;
    __syncthreads();
    if (isLast) {
        __threadfence();
        for (int idx = tid; idx < B * 128; idx += 384) {
            int c = idx & 127;
            float mu  = g_bn1[c] / (float)B;
            float var = g_bn2[c] / (float)B - mu * mu;
            float v = g_logits[idx];
            out[idx] = (v - mu) * rsqrtf(var + 1e-5f) * gamma[c] + beta[c];
        }
    }
}

// ---------------------------------------------------------------------------
// launch
// ---------------------------------------------------------------------------
extern "C" void kernel_launch(void* const* d_in, const int* in_sizes, int n_in,
                              void* d_out, int out_size) {
    const float* cell = (const float*)d_in[0];
    const float* Wd   = (const float*)d_in[1];
    const float* bd   = (const float*)d_in[2];
    const float* W1   = (const float*)d_in[3];
    const float* a1s  = (const float*)d_in[4];
    const float* a1d  = (const float*)d_in[5];
    const float* b1   = (const float*)d_in[6];
    const float* Wl1  = (const float*)d_in[7];
    const float* bl1  = (const float*)d_in[8];
    const float* W2   = (const float*)d_in[9];
    const float* a2s  = (const float*)d_in[10];
    const float* a2d  = (const float*)d_in[11];
    const float* b2   = (const float*)d_in[12];
    const float* Wl2  = (const float*)d_in[13];
    const float* bl2  = (const float*)d_in[14];
    const float* Wfc  = (const float*)d_in[15];
    const float* bfc  = (const float*)d_in[16];
    const float* Whg  = (const float*)d_in[17];
    const float* bhg  = (const float*)d_in[18];
    const float* Wc   = (const float*)d_in[19];
    const float* bc   = (const float*)d_in[20];
    const float* Wv   = (const float*)d_in[21];
    const float* bv   = (const float*)d_in[22];
    const float* Wq   = (const float*)d_in[23];
    const float* bq   = (const float*)d_in[24];
    const float* h_mat  = (const float*)d_in[25];
    const float* h_bias = (const float*)d_in[26];
    const float* gamma  = (const float*)d_in[27];
    const float* beta   = (const float*)d_in[28];
    const int*   trip   = (const int*)d_in[29];
    const int*   ei     = (const int*)d_in[30];

    int N  = in_sizes[29] / 4;
    int E  = in_sizes[30] / 2;
    int CF = in_sizes[19] / 128;
    int B  = in_sizes[0] / CF;
    int H1 = in_sizes[4] / 128;   // 4
    int H2 = in_sizes[10] / 128;  // 5
    int HOUT = in_sizes[26];
    if (N > NMAX) N = NMAX;
    if (E > EMAX) E = EMAX;
    float* out = (float*)d_out;

    void *ph1;
    void *pA2h, *pA2l, *pA3h, *pA3l;
    void *pb1h, *pb1l, *pb2h, *pb2l, *pb3h, *pb3l;
    cudaGetSymbolAddress(&ph1,  g_h1);
    cudaGetSymbolAddress(&pA2h, g_A2h);
    cudaGetSymbolAddress(&pA2l, g_A2l);
    cudaGetSymbolAddress(&pA3h, g_A3h);
    cudaGetSymbolAddress(&pA3l, g_A3l);
    cudaGetSymbolAddress(&pb1h, g_bt1h);
    cudaGetSymbolAddress(&pb1l, g_bt1l);
    cudaGetSymbolAddress(&pb2h, g_bt2h);
    cudaGetSymbolAddress(&pb2l, g_bt2l);
    cudaGetSymbolAddress(&pb3h, g_bt3h);
    cudaGetSymbolAddress(&pb3l, g_bt3l);

    cudaFuncSetAttribute(tgemm,    cudaFuncAttributeMaxDynamicSharedMemorySize, 49152);
    cudaFuncSetAttribute(tgemm_r4, cudaFuncAttributeMaxDynamicSharedMemorySize, 49152);

    int M1 = H1 * CDIM;  // 512
    int M2 = H2 * CDIM;  // 640
    int mt = (N + 63) / 64;

    // ---- prep ----
    int s0 = (N + 255) / 256;
    int s1 = (128 * M1 + 255) / 256;
    int s2 = (128 * 128 * H2 + 255) / 256;
    int s3 = (128 * M2 + 255) / 256;
    int s4 = (M1 + 255) / 256;
    int s5 = (CDIM * 2 * H2 + 255) / 256;
    prep_kernel<<<s0 + s1 + s2 + s3 + s4 + s5, 256>>>(Wl1, W2, Wl2, Wd, bd, W1,
                                                      a2s, a2d,
                                                      N, M1, M2, H2, s0, s1, s2, s3, s4);

    // ---- combined: count + es1 + q-precompute ----
    int c0 = (E / 8 + 255) / 256;
    int c1 = (N + 255) / 256;
    cnt_es1_q_kernel<<<c0 + c1 + B, 256>>>(ei, E, trip, a1s, a1d, N, M1,
                                           cell, Wc, bc, Wq, bq, CF, c0, c1);

    // ---- fused scan + fill ----
    scan_fill_kernel<<<1 + (E / 8 + 255) / 256, 256>>>(ei, E, N);

    // ---- GAT layer 1 ----
    agg_rank4_kernel<<<(N * 32 + 255) / 256, 256>>>(trip, N);
    tgemm_r4<<<dim3(1, mt, 1), 256, 49152>>>(
        b1, (const __nv_bfloat16*)pb1h, (const __nv_bfloat16*)pb1l,
        (float*)ph1, N, bl1);

    // ---- GAT layer 2 ----
    es2_kernel<<<(N + 7) / 8, 256>>>(N, H2);
    agg2_kernel<<<(N * 32 + 255) / 256, 256>>>((const float*)ph1, N);
    tgemm<<<dim3(1, mt, H2), 256, 49152>>>(
        (const __nv_bfloat16*)pA2h, (const __nv_bfloat16*)pA2l, M2, 128,
        (const __nv_bfloat16*)pb2h, (const __nv_bfloat16*)pb2l, 128 * 128,
        nullptr, (__nv_bfloat16*)pA3h, (__nv_bfloat16*)pA3l, M2, 128,
        N, 128, b2, 128, 1);
    tgemm<<<dim3(1, mt, 1), 256, 49152>>>(
        (const __nv_bfloat16*)pA3h, (const __nv_bfloat16*)pA3l, M2, 0,
        (const __nv_bfloat16*)pb3h, (const __nv_bfloat16*)pb3l, 0,
        nullptr, nullptr, nullptr, CDIM, 0, N, M2, bl2, 0, 0);

    // ---- fused tail ----
    tail_all_kernel<<<B + 1, 384>>>(Wfc, bfc, Whg, bhg, Wv, bv, h_mat, h_bias,
                                    gamma, beta, out, N, B, HOUT);
}

// round 16
// speedup vs baseline: 1.0695x; 1.0695x over previous
#include <cuda_runtime.h>
#include <cuda_bf16.h>
#include <math.h>
#include <stdint.h>

#define NMAX 20000
#define EMAX 500000
#define CDIM 128
#define NPAD (NMAX + 128)

// ---------------------------------------------------------------------------
// Static device scratch
// ---------------------------------------------------------------------------
__device__ float g_h1  [NMAX * CDIM];
__device__ float g_es  [NMAX * 4];
__device__ float g_ed  [NMAX * 4];
__device__ float g_es2p[NMAX * 8];
__device__ float g_ed2p[NMAX * 8];
__device__ float g_tt  [NMAX * 16];
__device__ int   g_cnt   [NMAX];
__device__ int   g_rowptr[NMAX + 1];
__device__ int   g_cursor[NMAX];
__device__ int   g_csrc  [EMAX];
__device__ float g_hsum  [CDIM];
__device__ float g_small [1024];
__device__ float g_logits[256 * CDIM];
__device__ float g_qrow  [256 * 384];
__device__ float g_bn1   [CDIM];
__device__ float g_bn2   [CDIM];
__device__ float g_Wp  [4 * 512];
__device__ float g_bp  [512];
__device__ float g_fold2[128 * 10];
__device__ __nv_bfloat16 g_A2h[NPAD * 640], g_A2l[NPAD * 640];
__device__ __nv_bfloat16 g_A3h[NPAD * 640], g_A3l[NPAD * 640];
__device__ __nv_bfloat16 g_bt1h[128 * 512], g_bt1l[128 * 512];
__device__ __nv_bfloat16 g_bt2h[5 * 128 * 128], g_bt2l[5 * 128 * 128];
__device__ __nv_bfloat16 g_bt3h[128 * 640], g_bt3l[128 * 640];

// ---------------------------------------------------------------------------
// helpers
// ---------------------------------------------------------------------------
__device__ __forceinline__ uint32_t smem_u32(const void* p) {
    uint32_t a;
    asm("{ .reg .u64 t; cvta.to.shared.u64 t, %1; cvt.u32.u64 %0, t; }" : "=r"(a) : "l"(p));
    return a;
}
__device__ __forceinline__ void ldsm4(uint32_t* r, uint32_t addr) {
    asm volatile("ldmatrix.sync.aligned.m8n8.x4.shared.b16 {%0,%1,%2,%3}, [%4];"
                 : "=r"(r[0]), "=r"(r[1]), "=r"(r[2]), "=r"(r[3]) : "r"(addr));
}
__device__ __forceinline__ void mma16816(float* d, const uint32_t* a, const uint32_t* b) {
    asm volatile(
        "mma.sync.aligned.m16n8k16.row.col.f32.bf16.bf16.f32 "
        "{%0,%1,%2,%3}, {%4,%5,%6,%7}, {%8,%9}, {%0,%1,%2,%3};"
        : "+f"(d[0]), "+f"(d[1]), "+f"(d[2]), "+f"(d[3])
        : "r"(a[0]), "r"(a[1]), "r"(a[2]), "r"(a[3]), "r"(b[0]), "r"(b[1]));
}
__device__ __forceinline__ uint32_t pack_bf(__nv_bfloat16 a, __nv_bfloat16 b) {
    __nv_bfloat162 t;
    t.x = a; t.y = b;
    return *reinterpret_cast<uint32_t*>(&t);
}
#define CPA(dst, src) \
    asm volatile("cp.async.cg.shared.global [%0], [%1], 16;" :: "r"(dst), "l"(src))

// ---------------------------------------------------------------------------
// prep: zero + 3x weight split + drug-linear fold + wfold2 (one launch)
// ---------------------------------------------------------------------------
__global__ void prep_kernel(const float* __restrict__ Wl1, const float* __restrict__ W2,
                            const float* __restrict__ Wl2, const float* __restrict__ Wd,
                            const float* __restrict__ bd,  const float* __restrict__ W1,
                            const float* __restrict__ a2s, const float* __restrict__ a2d,
                            int N, int M1, int M2, int H2,
                            int s0, int s1, int s2, int s3, int s4) {
    int b = blockIdx.x, tid = threadIdx.x;
    if (b < s0) {
        int i = b * 256 + tid;
        if (i < N) g_cnt[i] = 0;
        if (b == 0 && tid < CDIM) { g_hsum[tid] = 0.f; g_bn1[tid] = 0.f; g_bn2[tid] = 0.f; }
        return;
    }
    b -= s0;
    if (b < s1) {
        int idx = b * 256 + tid;
        if (idx < 128 * M1) {
            int j = idx / M1, k = idx - j * M1;
            float v = Wl1[(size_t)k * 128 + j];
            __nv_bfloat16 h = __float2bfloat16(v);
            g_bt1h[idx] = h;
            g_bt1l[idx] = __float2bfloat16(v - __bfloat162float(h));
        }
        return;
    }
    b -= s1;
    if (b < s2) {
        int idx = b * 256 + tid;
        if (idx < 128 * 128 * H2) {
            int z = idx / 16384, r = idx - z * 16384;
            int j = r / 128, k = r - j * 128;
            float v = W2[(size_t)k * M2 + z * 128 + j];
            __nv_bfloat16 h = __float2bfloat16(v);
            g_bt2h[idx] = h;
            g_bt2l[idx] = __float2bfloat16(v - __bfloat162float(h));
        }
        return;
    }
    b -= s2;
    if (b < s3) {
        int idx = b * 256 + tid;
        if (idx < 128 * M2) {
            int j = idx / M2, k = idx - j * M2;
            float v = Wl2[(size_t)k * 128 + j];
            __nv_bfloat16 h = __float2bfloat16(v);
            g_bt3h[idx] = h;
            g_bt3l[idx] = __float2bfloat16(v - __bfloat162float(h));
        }
        return;
    }
    b -= s3;
    if (b < s4) {
        int j = b * 256 + tid;
        if (j < M1) {
            float a0 = 0.f, a1 = 0.f, a2 = 0.f, a3 = 0.f, ab = 0.f;
#pragma unroll 4
            for (int k = 0; k < CDIM; k++) {
                float w = W1[k * M1 + j];
                a0 += Wd[0 * CDIM + k] * w;
                a1 += Wd[1 * CDIM + k] * w;
                a2 += Wd[2 * CDIM + k] * w;
                a3 += Wd[3 * CDIM + k] * w;
                ab += bd[k] * w;
            }
            g_Wp[0 * M1 + j] = a0;
            g_Wp[1 * M1 + j] = a1;
            g_Wp[2 * M1 + j] = a2;
            g_Wp[3 * M1 + j] = a3;
            g_bp[j] = ab;
        }
        return;
    }
    b -= s4;
    {
        int idx = b * 256 + tid;
        if (idx < CDIM * 2 * H2) {
            int c = idx / (2 * H2), o = idx - c * (2 * H2);
            int h = o % H2;
            const float* av = (o < H2) ? a2s : a2d;
            float s = 0.f;
            for (int k = 0; k < CDIM; k++) s += W2[c * M2 + h * CDIM + k] * av[h * CDIM + k];
            g_fold2[c * (2 * H2) + o] = s;
        }
    }
}

// ---------------------------------------------------------------------------
// combined: edge count (8 edges/thread) + layer-1 logits + q-precompute
// ---------------------------------------------------------------------------
__global__ void cnt_es1_q_kernel(const int* __restrict__ ei, int E,
                                 const int* __restrict__ trip,
                                 const float* __restrict__ a1s,
                                 const float* __restrict__ a1d, int N, int M1,
                                 const float* __restrict__ cell,
                                 const float* __restrict__ Wc, const float* __restrict__ bc,
                                 const float* __restrict__ Wq, const float* __restrict__ bq,
                                 int CF,
                                 int c0, int c1) {
    __shared__ float sm[1024];
    __shared__ float crow[128];
    int b = blockIdx.x, tid = threadIdx.x;
    if (b < c0) {                       // count (8 edges/thread)
        int e0 = (b * 256 + tid) * 8;
#pragma unroll
        for (int j = 0; j < 8; j += 2) {
            int e = e0 + j;
            if (e + 1 < E) {
                int2 s = *(const int2*)(ei + e);
                int2 d = *(const int2*)(ei + E + e);
                if (s.x != d.x) atomicAdd(&g_cnt[d.x], 1);
                if (s.y != d.y) atomicAdd(&g_cnt[d.y], 1);
            } else if (e < E) {
                int s = ei[e], d = ei[E + e];
                if (s != d) atomicAdd(&g_cnt[d], 1);
            }
        }
        return;
    }
    b -= c0;
    if (b < c1) {                       // es1
        float* f1 = sm;
        if (tid < 16) {
            int h = tid >> 2, i = tid & 3;
            float s = 0.f;
            for (int k = 0; k < CDIM; k++) s += g_Wp[i * M1 + h * CDIM + k] * a1s[h * CDIM + k];
            f1[tid] = s;
        } else if (tid < 32) {
            int t = tid - 16;
            int h = t >> 2, i = t & 3;
            float s = 0.f;
            for (int k = 0; k < CDIM; k++) s += g_Wp[i * M1 + h * CDIM + k] * a1d[h * CDIM + k];
            f1[tid] = s;
        } else if (tid < 36) {
            int h = tid - 32;
            float s = 0.f;
            for (int k = 0; k < CDIM; k++) s += g_bp[h * CDIM + k] * a1s[h * CDIM + k];
            f1[tid] = s;
        } else if (tid < 40) {
            int h = tid - 36;
            float s = 0.f;
            for (int k = 0; k < CDIM; k++) s += g_bp[h * CDIM + k] * a1d[h * CDIM + k];
            f1[tid] = s;
        }
        __syncthreads();
        int n = b * 256 + tid;
        if (n >= N) return;
        int4 tv = *(const int4*)(trip + n * 4);
        float t0 = (float)tv.x, t1 = (float)tv.y, t2 = (float)tv.z, t3 = (float)tv.w;
        float4 es, ed;
        float* esp = &es.x;
        float* edp = &ed.x;
#pragma unroll
        for (int h = 0; h < 4; h++) {
            esp[h] = f1[32 + h] + t0 * f1[h * 4 + 0] + t1 * f1[h * 4 + 1]
                   + t2 * f1[h * 4 + 2] + t3 * f1[h * 4 + 3];
            edp[h] = f1[36 + h] + t0 * f1[16 + h * 4 + 0] + t1 * f1[16 + h * 4 + 1]
                   + t2 * f1[16 + h * 4 + 2] + t3 * f1[16 + h * 4 + 3];
        }
        *(float4*)(g_es + n * 4) = es;
        *(float4*)(g_ed + n * 4) = ed;
        return;
    }
    b -= c1;
    {                                   // q precompute for batch row b
        for (int i = tid; i < CF; i += 256) sm[i] = cell[(size_t)b * CF + i];
        __syncthreads();
        if (tid < 128) {
            float a = bc[tid];
            for (int k = 0; k < CF; k++) a += sm[k] * Wc[k * 128 + tid];
            crow[tid] = a > 0.f ? a : 0.f;
        }
        __syncthreads();
        for (int mI = tid; mI < 384; mI += 256) {
            float q = bq[mI];
            for (int k = 0; k < 128; k++) q += crow[k] * Wq[k * 384 + mI];
            g_qrow[b * 384 + mI] = q > 0.f ? q : 0.f;
        }
    }
}

// ---------------------------------------------------------------------------
// scan (vectorized single block, 1024 threads)
// ---------------------------------------------------------------------------
__global__ void scan_kernel(int N) {
    __shared__ int wsum[32];
    __shared__ int carry_s;
    int tid = threadIdx.x, lane = tid & 31, wid = tid >> 5;
    if (tid == 0) { carry_s = 0; g_rowptr[0] = 0; }
    __syncthreads();
    int NT = (N + 3) >> 2;
    for (int base = 0; base < NT; base += 1024) {
        int i4 = base + tid;
        int b0 = i4 * 4;
        int4 v = make_int4(0, 0, 0, 0);
        if (b0 + 3 < N) {
            v = *(const int4*)(g_cnt + b0);
        } else if (b0 < N) {
            v.x = g_cnt[b0];
            if (b0 + 1 < N) v.y = g_cnt[b0 + 1];
            if (b0 + 2 < N) v.z = g_cnt[b0 + 2];
        }
        int p1 = v.x, p2 = p1 + v.y, p3 = p2 + v.z, p4 = p3 + v.w;
        int x = p4;
#pragma unroll
        for (int o = 1; o < 32; o <<= 1) {
            int t = __shfl_up_sync(0xffffffffu, x, o);
            if (lane >= o) x += t;
        }
        if (lane == 31) wsum[wid] = x;
        __syncthreads();
        if (wid == 0) {
            int s = wsum[lane];
#pragma unroll
            for (int o = 1; o < 32; o <<= 1) {
                int t = __shfl_up_sync(0xffffffffu, s, o);
                if (lane >= o) s += t;
            }
            wsum[lane] = s;
        }
        __syncthreads();
        int pre = carry_s + (wid ? wsum[wid - 1] : 0) + (x - p4);
        if (b0 < N)     { g_rowptr[b0 + 1] = pre + p1; g_cursor[b0]     = pre; }
        if (b0 + 1 < N) { g_rowptr[b0 + 2] = pre + p2; g_cursor[b0 + 1] = pre + p1; }
        if (b0 + 2 < N) { g_rowptr[b0 + 3] = pre + p3; g_cursor[b0 + 2] = pre + p2; }
        if (b0 + 3 < N) { g_rowptr[b0 + 4] = pre + p4; g_cursor[b0 + 3] = pre + p3; }
        __syncthreads();
        if (tid == 0) carry_s += wsum[31];
        __syncthreads();
    }
}

// fill (8 edges/thread)
__global__ void fill_kernel(const int* __restrict__ ei, int E) {
    int e0 = (blockIdx.x * blockDim.x + threadIdx.x) * 8;
#pragma unroll
    for (int j = 0; j < 8; j += 2) {
        int e = e0 + j;
        if (e + 1 < E) {
            int2 s = *(const int2*)(ei + e);
            int2 d = *(const int2*)(ei + E + e);
            if (s.x != d.x) { int p = atomicAdd(&g_cursor[d.x], 1); g_csrc[p] = s.x; }
            if (s.y != d.y) { int p = atomicAdd(&g_cursor[d.y], 1); g_csrc[p] = s.y; }
        } else if (e < E) {
            int s = ei[e], d = ei[E + e];
            if (s != d) { int p = atomicAdd(&g_cursor[d], 1); g_csrc[p] = s; }
        }
    }
}

// ---------------------------------------------------------------------------
// Layer-1 aggregation
// ---------------------------------------------------------------------------
__global__ void agg_rank4_kernel(const int* __restrict__ trip, int N) {
    const int H = 4;
    int warp = (blockIdx.x * blockDim.x + threadIdx.x) >> 5;
    int lane = threadIdx.x & 31;
    if (warp >= N) return;
    int n   = warp;
    int r0  = g_rowptr[n];
    int deg = g_rowptr[n + 1] - r0;
    int tot = deg + 1;

    float4 edv4 = *(const float4*)(g_ed + n * 4);
    float edv[H] = {edv4.x, edv4.y, edv4.z, edv4.w};
    float m[H] = {-1e30f, -1e30f, -1e30f, -1e30f};
    for (int i = lane; i < tot; i += 32) {
        int src = (i < deg) ? g_csrc[r0 + i] : n;
        float4 es = *(const float4*)(g_es + src * 4);
        float ev[H] = {es.x, es.y, es.z, es.w};
#pragma unroll
        for (int h = 0; h < H; h++) {
            float e = ev[h] + edv[h];
            e = e > 0.f ? e : 0.2f * e;
            m[h] = fmaxf(m[h], e);
        }
    }
#pragma unroll
    for (int h = 0; h < H; h++)
        for (int o = 16; o; o >>= 1) m[h] = fmaxf(m[h], __shfl_xor_sync(0xffffffffu, m[h], o));
    float4 acc[H];
    float z[H];
#pragma unroll
    for (int h = 0; h < H; h++) { acc[h] = make_float4(0.f, 0.f, 0.f, 0.f); z[h] = 0.f; }
    for (int i = lane; i < tot; i += 32) {
        int src = (i < deg) ? g_csrc[r0 + i] : n;
        float4 es = *(const float4*)(g_es + src * 4);
        float ev[H] = {es.x, es.y, es.z, es.w};
        int4 tv = *(const int4*)(trip + src * 4);
        float4 tf = make_float4((float)tv.x, (float)tv.y, (float)tv.z, (float)tv.w);
#pragma unroll
        for (int h = 0; h < H; h++) {
            float e = ev[h] + edv[h];
            e = e > 0.f ? e : 0.2f * e;
            float w = __expf(e - m[h]);
            z[h] += w;
            acc[h].x += w * tf.x; acc[h].y += w * tf.y;
            acc[h].z += w * tf.z; acc[h].w += w * tf.w;
        }
    }
#pragma unroll
    for (int h = 0; h < H; h++) {
        for (int o = 16; o; o >>= 1) {
            acc[h].x += __shfl_xor_sync(0xffffffffu, acc[h].x, o);
            acc[h].y += __shfl_xor_sync(0xffffffffu, acc[h].y, o);
            acc[h].z += __shfl_xor_sync(0xffffffffu, acc[h].z, o);
            acc[h].w += __shfl_xor_sync(0xffffffffu, acc[h].w, o);
            z[h]     += __shfl_xor_sync(0xffffffffu, z[h], o);
        }
    }
    if (lane == 0) {
#pragma unroll
        for (int h = 0; h < H; h++) {
            float iz = 1.f / z[h];
            float4 r = make_float4(acc[h].x * iz, acc[h].y * iz, acc[h].z * iz, acc[h].w * iz);
            *(float4*)(g_tt + n * 16 + h * 4) = r;
        }
    }
}

// ---------------------------------------------------------------------------
// tgemm_r4: 64-row tile, 2-stage, 3 CTA/SM, colsum epilogue
// smem: A 2x8KB @0, B 2x16KB @16384 -> 49152 B.
// ---------------------------------------------------------------------------
__global__ void __launch_bounds__(256, 3)
tgemm_r4(const float* __restrict__ b1,
         const __nv_bfloat16* __restrict__ Bh, const __nv_bfloat16* __restrict__ Bl,
         float* __restrict__ Cf, int M, const float* __restrict__ cbias) {
    const int K = 512;
    extern __shared__ __align__(16) char dsm[];
    char*    sAc = dsm;
    uint32_t sAu = smem_u32(dsm);
    uint32_t sBu = sAu + 16384;

    int tid  = threadIdx.x;
    int wid  = tid >> 5;
    int lane = tid & 31;
    int m0   = blockIdx.y * 64;
    int wm   = wid & 1;
    int wn   = wid >> 1;

    float acc[2][4][4];
#pragma unroll
    for (int i = 0; i < 2; i++)
#pragma unroll
        for (int j = 0; j < 4; j++)
#pragma unroll
            for (int l = 0; l < 4; l++) acc[i][j][l] = 0.f;

#define STAGEB(BUF, KC)                                                        \
    {                                                                          \
        int _kc = (KC);                                                        \
        _Pragma("unroll")                                                      \
        for (int it = 0; it < 4; it++) {                                       \
            int idx = it * 256 + tid;                                          \
            int row = idx >> 3, ch = idx & 7;                                  \
            const __nv_bfloat16* gs = ((ch < 4) ? Bh : Bl)                     \
                + (size_t)row * K + _kc + (ch & 3) * 8;                        \
            uint32_t dst = sBu + (BUF) * 16384 + row * 128                     \
                + ((ch ^ (row & 7)) << 4);                                     \
            CPA(dst, gs);                                                      \
        }                                                                      \
    }

#define STAGEA(BUF, KC)                                                        \
    {                                                                          \
        int _kc = (KC);                                                        \
        int _h  = _kc >> 7;                                                    \
        _Pragma("unroll")                                                      \
        for (int it = 0; it < 2; it++) {                                       \
            int idx = it * 256 + tid;                                          \
            int row = idx >> 3, cg = idx & 7;                                  \
            int gr = m0 + row; if (gr >= M) gr = M - 1;                        \
            float4 t = *(const float4*)(g_tt + gr * 16 + _h * 4);              \
            int j = _kc + cg * 4;                                              \
            float4 w0 = *(const float4*)(g_Wp + 0 * 512 + j);                  \
            float4 w1 = *(const float4*)(g_Wp + 1 * 512 + j);                  \
            float4 w2 = *(const float4*)(g_Wp + 2 * 512 + j);                  \
            float4 w3 = *(const float4*)(g_Wp + 3 * 512 + j);                  \
            float4 bb = *(const float4*)(g_bp + j);                            \
            float4 b2v = *(const float4*)(b1 + j);                             \
            float v0 = bb.x + b2v.x + t.x * w0.x + t.y * w1.x + t.z * w2.x + t.w * w3.x; \
            float v1 = bb.y + b2v.y + t.x * w0.y + t.y * w1.y + t.z * w2.y + t.w * w3.y; \
            float v2 = bb.z + b2v.z + t.x * w0.z + t.y * w1.z + t.z * w2.z + t.w * w3.z; \
            float v3 = bb.w + b2v.w + t.x * w0.w + t.y * w1.w + t.z * w2.w + t.w * w3.w; \
            v0 = v0 > 0.f ? v0 : __expf(v0) - 1.f;                             \
            v1 = v1 > 0.f ? v1 : __expf(v1) - 1.f;                             \
            v2 = v2 > 0.f ? v2 : __expf(v2) - 1.f;                             \
            v3 = v3 > 0.f ? v3 : __expf(v3) - 1.f;                             \
            __nv_bfloat16 h0 = __float2bfloat16(v0);                           \
            __nv_bfloat16 h1 = __float2bfloat16(v1);                           \
            __nv_bfloat16 h2 = __float2bfloat16(v2);                           \
            __nv_bfloat16 h3 = __float2bfloat16(v3);                           \
            uint2 hi2 = make_uint2(pack_bf(h0, h1), pack_bf(h2, h3));          \
            uint2 lo2 = make_uint2(                                            \
                pack_bf(__float2bfloat16(v0 - __bfloat162float(h0)),           \
                        __float2bfloat16(v1 - __bfloat162float(h1))),          \
                pack_bf(__float2bfloat16(v2 - __bfloat162float(h2)),           \
                        __float2bfloat16(v3 - __bfloat162float(h3))));         \
            int ch = cg >> 1, rem = (cg & 1) * 8;                              \
            char* base = sAc + (BUF) * 8192 + row * 128;                       \
            *(uint2*)(base + (((ch)     ^ (row & 7)) << 4) + rem) = hi2;       \
            *(uint2*)(base + (((ch + 4) ^ (row & 7)) << 4) + rem) = lo2;       \
        }                                                                      \
    }

    int nk = K >> 5;
    STAGEB(0, 0)
    asm volatile("cp.async.commit_group;");
    STAGEA(0, 0)

    for (int i = 0; i < nk; i++) {
        int buf = i & 1;
        if (i + 1 < nk) {
            STAGEB(buf ^ 1, (i + 1) * 32)
            asm volatile("cp.async.commit_group;");
            STAGEA(buf ^ 1, (i + 1) * 32)
            asm volatile("cp.async.wait_group 1;");
        } else {
            asm volatile("cp.async.wait_group 0;");
        }
        __syncthreads();

        uint32_t a_base = sAu + buf * 8192;
        uint32_t b_base = sBu + buf * 16384;
#pragma unroll
        for (int ks = 0; ks < 2; ks++) {
            uint32_t ah[2][4], al[2][4], bh[2][4], bl[2][4];
            int arow = (lane & 7) + ((lane >> 3) & 1) * 8;
            int akg  = 2 * ks + (lane >> 4);
#pragma unroll
            for (int mf = 0; mf < 2; mf++) {
                int r = 32 * wm + 16 * mf + arow;
                ldsm4(ah[mf], a_base + r * 128 + (((akg)     ^ (r & 7)) << 4));
                ldsm4(al[mf], a_base + r * 128 + (((akg + 4) ^ (r & 7)) << 4));
            }
            int brow = (lane & 7) + (lane >> 4) * 8;
            int bkg  = 2 * ks + ((lane >> 3) & 1);
#pragma unroll
            for (int q = 0; q < 2; q++) {
                int r = 32 * wn + 16 * q + brow;
                ldsm4(bh[q], b_base + r * 128 + (((bkg)     ^ (r & 7)) << 4));
                ldsm4(bl[q], b_base + r * 128 + (((bkg + 4) ^ (r & 7)) << 4));
            }
#pragma unroll
            for (int mf = 0; mf < 2; mf++) {
#pragma unroll
                for (int q = 0; q < 2; q++) {
                    mma16816(acc[mf][2 * q + 0], ah[mf], &bh[q][0]);
                    mma16816(acc[mf][2 * q + 1], ah[mf], &bh[q][2]);
                    mma16816(acc[mf][2 * q + 0], al[mf], &bh[q][0]);
                    mma16816(acc[mf][2 * q + 1], al[mf], &bh[q][2]);
                    mma16816(acc[mf][2 * q + 0], ah[mf], &bl[q][0]);
                    mma16816(acc[mf][2 * q + 1], ah[mf], &bl[q][2]);
                }
            }
        }
        __syncthreads();
    }
#undef STAGEA
#undef STAGEB

    float* colsum = (float*)dsm;
    if (tid < 128) colsum[tid] = 0.f;
    __syncthreads();
#pragma unroll
    for (int mf = 0; mf < 2; mf++) {
        int r0 = m0 + 32 * wm + 16 * mf + (lane >> 2);
#pragma unroll
        for (int nf = 0; nf < 4; nf++) {
            int col = 32 * wn + 8 * nf + 2 * (lane & 3);
            float cb0 = cbias[col], cb1 = cbias[col + 1];
            float s0 = 0.f, s1 = 0.f;
#pragma unroll
            for (int rr = 0; rr < 2; rr++) {
                int r = r0 + rr * 8;
                if (r >= M) continue;
                float v0 = acc[mf][nf][2 * rr + 0] + cb0;
                float v1 = acc[mf][nf][2 * rr + 1] + cb1;
                *(float2*)(Cf + (size_t)r * CDIM + col) = make_float2(v0, v1);
                s0 += v0; s1 += v1;
            }
            atomicAdd(&colsum[col], s0);
            atomicAdd(&colsum[col + 1], s1);
        }
    }
    __syncthreads();
    if (tid < 128) atomicAdd(&g_hsum[tid], colsum[tid]);
}

// ---------------------------------------------------------------------------
// generic tgemm: 64-row tile, 2-stage, 3 CTA/SM (R13-exact smem layout)
// smem: A 2x8KB @0, B 2x16KB @16384 -> 49152 B.
// ---------------------------------------------------------------------------
__global__ void __launch_bounds__(256, 3)
tgemm(const __nv_bfloat16* __restrict__ Ah, const __nv_bfloat16* __restrict__ Al,
      int lda, int boa,
      const __nv_bfloat16* __restrict__ Bh, const __nv_bfloat16* __restrict__ Bl, int bob,
      float* __restrict__ Cf, __nv_bfloat16* __restrict__ Ch, __nv_bfloat16* __restrict__ Cl,
      int ldc, int boc,
      int M, int K, const float* __restrict__ cbias, int bocb, int celu) {
    Ah += (size_t)blockIdx.z * boa;
    Al += (size_t)blockIdx.z * boa;
    Bh += (size_t)blockIdx.z * bob;
    Bl += (size_t)blockIdx.z * bob;
    if (Cf) Cf += (size_t)blockIdx.z * boc;
    if (Ch) { Ch += (size_t)blockIdx.z * boc; Cl += (size_t)blockIdx.z * boc; }
    cbias += (size_t)blockIdx.z * bocb;
    int sum_only = (Cf == nullptr) && (Ch == nullptr);

    extern __shared__ __align__(16) char dsm[];
    uint32_t sAu = smem_u32(dsm);
    uint32_t sBu = sAu + 16384;

    int tid  = threadIdx.x;
    int wid  = tid >> 5;
    int lane = tid & 31;
    int m0   = blockIdx.y * 64;
    int wm   = wid & 1;
    int wn   = wid >> 1;

    float acc[2][4][4];
#pragma unroll
    for (int i = 0; i < 2; i++)
#pragma unroll
        for (int j = 0; j < 4; j++)
#pragma unroll
            for (int l = 0; l < 4; l++) acc[i][j][l] = 0.f;

#define STAGE(BUF, KC)                                                         \
    {                                                                          \
        int _kc = (KC);                                                        \
        _Pragma("unroll")                                                      \
        for (int it = 0; it < 2; it++) {                                       \
            int idx = it * 256 + tid;                                          \
            int row = idx >> 3, ch = idx & 7;                                  \
            const __nv_bfloat16* gs = ((ch < 4) ? Ah : Al)                     \
                + (size_t)(m0 + row) * lda + _kc + (ch & 3) * 8;               \
            uint32_t dst = sAu + (BUF) * 8192 + row * 128                      \
                + ((ch ^ (row & 7)) << 4);                                     \
            CPA(dst, gs);                                                      \
        }                                                                      \
        _Pragma("unroll")                                                      \
        for (int it = 0; it < 4; it++) {                                       \
            int idx = it * 256 + tid;                                          \
            int row = idx >> 3, ch = idx & 7;                                  \
            const __nv_bfloat16* gs = ((ch < 4) ? Bh : Bl)                     \
                + (size_t)row * K + _kc + (ch & 3) * 8;                        \
            uint32_t dst = sBu + (BUF) * 16384 + row * 128                     \
                + ((ch ^ (row & 7)) << 4);                                     \
            CPA(dst, gs);                                                      \
        }                                                                      \
    }

    int nk = K >> 5;
    STAGE(0, 0)
    asm volatile("cp.async.commit_group;");

    for (int i = 0; i < nk; i++) {
        int buf = i & 1;
        if (i + 1 < nk) {
            STAGE(buf ^ 1, (i + 1) * 32)
            asm volatile("cp.async.commit_group;");
            asm volatile("cp.async.wait_group 1;");
        } else {
            asm volatile("cp.async.wait_group 0;");
        }
        __syncthreads();

        uint32_t a_base = sAu + buf * 8192;
        uint32_t b_base = sBu + buf * 16384;
#pragma unroll
        for (int ks = 0; ks < 2; ks++) {
            uint32_t ah[2][4], al[2][4], bh[2][4], bl[2][4];
            int arow = (lane & 7) + ((lane >> 3) & 1) * 8;
            int akg  = 2 * ks + (lane >> 4);
#pragma unroll
            for (int mf = 0; mf < 2; mf++) {
                int r = 32 * wm + 16 * mf + arow;
                ldsm4(ah[mf], a_base + r * 128 + (((akg)     ^ (r & 7)) << 4));
                ldsm4(al[mf], a_base + r * 128 + (((akg + 4) ^ (r & 7)) << 4));
            }
            int brow = (lane & 7) + (lane >> 4) * 8;
            int bkg  = 2 * ks + ((lane >> 3) & 1);
#pragma unroll
            for (int q = 0; q < 2; q++) {
                int r = 32 * wn + 16 * q + brow;
                ldsm4(bh[q], b_base + r * 128 + (((bkg)     ^ (r & 7)) << 4));
                ldsm4(bl[q], b_base + r * 128 + (((bkg + 4) ^ (r & 7)) << 4));
            }
#pragma unroll
            for (int mf = 0; mf < 2; mf++) {
#pragma unroll
                for (int q = 0; q < 2; q++) {
                    mma16816(acc[mf][2 * q + 0], ah[mf], &bh[q][0]);
                    mma16816(acc[mf][2 * q + 1], ah[mf], &bh[q][2]);
                    mma16816(acc[mf][2 * q + 0], al[mf], &bh[q][0]);
                    mma16816(acc[mf][2 * q + 1], al[mf], &bh[q][2]);
                    mma16816(acc[mf][2 * q + 0], ah[mf], &bl[q][0]);
                    mma16816(acc[mf][2 * q + 1], ah[mf], &bl[q][2]);
                }
            }
        }
        __syncthreads();
    }
#undef STAGE

    float* colsum = (float*)dsm;
    if (sum_only) {
        if (tid < 128) colsum[tid] = 0.f;
        __syncthreads();
    }
#pragma unroll
    for (int mf = 0; mf < 2; mf++) {
        int r0 = m0 + 32 * wm + 16 * mf + (lane >> 2);
#pragma unroll
        for (int nf = 0; nf < 4; nf++) {
            int col = 32 * wn + 8 * nf + 2 * (lane & 3);
            float cb0 = cbias[col], cb1 = cbias[col + 1];
            float s0 = 0.f, s1 = 0.f;
#pragma unroll
            for (int rr = 0; rr < 2; rr++) {
                int r = r0 + rr * 8;
                if (r >= M) continue;
                float v0 = acc[mf][nf][2 * rr + 0] + cb0;
                float v1 = acc[mf][nf][2 * rr + 1] + cb1;
                if (Cf) {
                    *(float2*)(Cf + (size_t)r * ldc + col) = make_float2(v0, v1);
                } else if (Ch) {
                    if (celu) {
                        v0 = v0 > 0.f ? v0 : __expf(v0) - 1.f;
                        v1 = v1 > 0.f ? v1 : __expf(v1) - 1.f;
                    }
                    __nv_bfloat16 h0 = __float2bfloat16(v0);
                    __nv_bfloat16 h1 = __float2bfloat16(v1);
                    size_t o = (size_t)r * ldc + col;
                    *(uint32_t*)(Ch + o) = pack_bf(h0, h1);
                    *(uint32_t*)(Cl + o) =
                        pack_bf(__float2bfloat16(v0 - __bfloat162float(h0)),
                                __float2bfloat16(v1 - __bfloat162float(h1)));
                } else {
                    s0 += v0; s1 += v1;
                }
            }
            if (sum_only) {
                atomicAdd(&colsum[col], s0);
                atomicAdd(&colsum[col + 1], s1);
            }
        }
    }
    if (sum_only) {
        __syncthreads();
        if (tid < 128) atomicAdd(&g_hsum[tid], colsum[tid]);
    }
}

// ---------------------------------------------------------------------------
// es2
// ---------------------------------------------------------------------------
__global__ void es2_kernel(int N, int H) {
    __shared__ float wt[CDIM * 10];
    int tid = threadIdx.x;
    int TW = CDIM * 2 * H;
    for (int i = tid; i < TW; i += blockDim.x) wt[i] = g_fold2[i];
    __syncthreads();
    int warp = blockIdx.x * (blockDim.x >> 5) + (tid >> 5);
    int lane = tid & 31;
    if (warp >= N) return;
    float4 hv = *(const float4*)(g_h1 + (size_t)warp * CDIM + lane * 4);
    float s[10];
#pragma unroll
    for (int o = 0; o < 10; o++) s[o] = 0.f;
    float hvv[4] = {hv.x, hv.y, hv.z, hv.w};
#pragma unroll
    for (int j = 0; j < 4; j++) {
        int c = lane * 4 + j;
        for (int o = 0; o < 2 * H; o++) s[o] += hvv[j] * wt[c * (2 * H) + o];
    }
    for (int o = 0; o < 2 * H; o++)
        for (int off = 16; off; off >>= 1) s[o] += __shfl_xor_sync(0xffffffffu, s[o], off);
    if (lane < H)          g_es2p[warp * 8 + lane] = s[lane];
    else if (lane < 2 * H) g_ed2p[warp * 8 + lane - H] = s[lane];
}

// ---------------------------------------------------------------------------
// Layer-2 aggregation
// ---------------------------------------------------------------------------
__global__ void agg2_kernel(const float* __restrict__ feat, int N) {
    const int H = 5;
    int warp = (blockIdx.x * blockDim.x + threadIdx.x) >> 5;
    int lane = threadIdx.x & 31;
    if (warp >= N) return;
    int n   = warp;
    int r0  = g_rowptr[n];
    int deg = g_rowptr[n + 1] - r0;
    int tot = deg + 1;

    float edv[H], m[H];
    {
        float4 e4 = *(const float4*)(g_ed2p + n * 8);
        edv[0] = e4.x; edv[1] = e4.y; edv[2] = e4.z; edv[3] = e4.w;
        edv[4] = g_ed2p[n * 8 + 4];
    }
#pragma unroll
    for (int h = 0; h < H; h++) m[h] = -1e30f;
    for (int i = lane; i < tot; i += 32) {
        int src = (i < deg) ? g_csrc[r0 + i] : n;
        float4 e4 = *(const float4*)(g_es2p + src * 8);
        float ev[H] = {e4.x, e4.y, e4.z, e4.w, g_es2p[src * 8 + 4]};
#pragma unroll
        for (int h = 0; h < H; h++) {
            float e = ev[h] + edv[h];
            e = e > 0.f ? e : 0.2f * e;
            m[h] = fmaxf(m[h], e);
        }
    }
#pragma unroll
    for (int h = 0; h < H; h++)
        for (int o = 16; o; o >>= 1) m[h] = fmaxf(m[h], __shfl_xor_sync(0xffffffffu, m[h], o));

    float4 acc[H];
    float zp[H];
#pragma unroll
    for (int h = 0; h < H; h++) { acc[h] = make_float4(0.f, 0.f, 0.f, 0.f); zp[h] = 0.f; }

    for (int t = 0; t < tot; t += 32) {
        int i = t + lane;
        int src = n;
        float w[H];
        if (i < tot) {
            src = (i < deg) ? g_csrc[r0 + i] : n;
            float4 e4 = *(const float4*)(g_es2p + src * 8);
            float ev[H] = {e4.x, e4.y, e4.z, e4.w, g_es2p[src * 8 + 4]};
#pragma unroll
            for (int h = 0; h < H; h++) {
                float e = ev[h] + edv[h];
                e = e > 0.f ? e : 0.2f * e;
                w[h] = __expf(e - m[h]);
                zp[h] += w[h];
            }
        } else {
#pragma unroll
            for (int h = 0; h < H; h++) w[h] = 0.f;
        }
        int cnt = tot - t;
        if (cnt > 32) cnt = 32;
#pragma unroll 4
        for (int j = 0; j < cnt; j++) {
            int s = __shfl_sync(0xffffffffu, src, j);
            float wj[H];
#pragma unroll
            for (int h = 0; h < H; h++) wj[h] = __shfl_sync(0xffffffffu, w[h], j);
            float4 v = *(const float4*)(feat + (size_t)s * CDIM + lane * 4);
#pragma unroll
            for (int h = 0; h < H; h++) {
                acc[h].x += wj[h] * v.x; acc[h].y += wj[h] * v.y;
                acc[h].z += wj[h] * v.z; acc[h].w += wj[h] * v.w;
            }
        }
    }
#pragma unroll
    for (int h = 0; h < H; h++)
        for (int o = 16; o; o >>= 1) zp[h] += __shfl_xor_sync(0xffffffffu, zp[h], o);

#pragma unroll
    for (int h = 0; h < H; h++) {
        float iz = 1.f / zp[h];
        float ax = acc[h].x * iz, ay = acc[h].y * iz;
        float az = acc[h].z * iz, aw = acc[h].w * iz;
        __nv_bfloat16 hx = __float2bfloat16(ax);
        __nv_bfloat16 hy = __float2bfloat16(ay);
        __nv_bfloat16 hz = __float2bfloat16(az);
        __nv_bfloat16 hw = __float2bfloat16(aw);
        size_t o = (size_t)n * (H * CDIM) + h * CDIM + lane * 4;
        *(uint2*)(g_A2h + o) = make_uint2(pack_bf(hx, hy), pack_bf(hz, hw));
        *(uint2*)(g_A2l + o) = make_uint2(
            pack_bf(__float2bfloat16(ax - __bfloat162float(hx)),
                    __float2bfloat16(ay - __bfloat162float(hy))),
            pack_bf(__float2bfloat16(az - __bfloat162float(hz)),
                    __float2bfloat16(aw - __bfloat162float(hw))));
    }
}

// ---------------------------------------------------------------------------
// tails (R13 structure)
// ---------------------------------------------------------------------------
__global__ void tail0_kernel(const float* __restrict__ Wfc, const float* __restrict__ bfc,
                             const float* __restrict__ Whg, const float* __restrict__ bhg,
                             const float* __restrict__ Wv,  const float* __restrict__ bv,
                             const float* __restrict__ h_mat, const float* __restrict__ h_bias,
                             int N, int HOUT) {
    __shared__ float h[128];
    __shared__ float tm[256];
    __shared__ float hg[128];
    int tid = threadIdx.x;
    if (tid < 128) h[tid] = g_hsum[tid] / (float)N;
    __syncthreads();
    if (tid < 256) {
        float a = bfc[tid];
        for (int i = 0; i < 128; i++) a += h[i] * Wfc[i * 256 + tid];
        tm[tid] = a > 0.f ? a : 0.f;
    }
    __syncthreads();
    if (tid < 128) {
        float a = bhg[tid];
        for (int i = 0; i < 256; i++) a += tm[i] * Whg[i * 128 + tid];
        hg[tid] = a;
    }
    __syncthreads();
    if (tid < 384) {
        float a = bv[tid];
        for (int i = 0; i < 128; i++) a += hg[i] * Wv[i * 384 + tid];
        g_small[tid] = a > 0.f ? a : 0.f;
        float hs = 0.f;
        for (int hh = 0; hh < HOUT; hh++) hs += h_mat[hh * 384 + tid];
        g_small[384 + tid] = hs;
    }
    if (tid == 0) {
        float hb = 0.f;
        for (int i = 0; i < HOUT; i++) hb += h_bias[i];
        g_small[768] = hb;
    }
}

__global__ void tail1_kernel(int B) {
    __shared__ float red[128];
    int b = blockIdx.x, tid = threadIdx.x;  // 128 threads
    float part = 0.f;
    for (int mI = tid; mI < 384; mI += 128)
        part += g_small[384 + mI] * g_small[mI] * g_qrow[b * 384 + mI];
    red[tid] = part;
    __syncthreads();
    for (int o = 64; o; o >>= 1) {
        if (tid < o) red[tid] += red[tid + o];
        __syncthreads();
    }
    float att = red[0] + g_small[768];
    float l = 0.f;
#pragma unroll
    for (int j = 0; j < 3; j++) {
        int k = tid * 3 + j;
        l += g_small[k] * g_qrow[b * 384 + k];
    }
    float v = att * l;
    g_logits[b * 128 + tid] = v;
    atomicAdd(&g_bn1[tid], v);
    atomicAdd(&g_bn2[tid], v * v);
}

__global__ void tail2_kernel(const float* __restrict__ gamma,
                             const float* __restrict__ beta,
                             float* __restrict__ out, int B) {
    int idx = blockIdx.x * blockDim.x + threadIdx.x;
    if (idx >= B * 128) return;
    int c = idx & 127;
    float mu  = g_bn1[c] / (float)B;
    float var = g_bn2[c] / (float)B - mu * mu;
    float v = g_logits[idx];
    out[idx] = (v - mu) * rsqrtf(var + 1e-5f) * gamma[c] + beta[c];
}

// ---------------------------------------------------------------------------
// launch
// ---------------------------------------------------------------------------
extern "C" void kernel_launch(void* const* d_in, const int* in_sizes, int n_in,
                              void* d_out, int out_size) {
    const float* cell = (const float*)d_in[0];
    const float* Wd   = (const float*)d_in[1];
    const float* bd   = (const float*)d_in[2];
    const float* W1   = (const float*)d_in[3];
    const float* a1s  = (const float*)d_in[4];
    const float* a1d  = (const float*)d_in[5];
    const float* b1   = (const float*)d_in[6];
    const float* Wl1  = (const float*)d_in[7];
    const float* bl1  = (const float*)d_in[8];
    const float* W2   = (const float*)d_in[9];
    const float* a2s  = (const float*)d_in[10];
    const float* a2d  = (const float*)d_in[11];
    const float* b2   = (const float*)d_in[12];
    const float* Wl2  = (const float*)d_in[13];
    const float* bl2  = (const float*)d_in[14];
    const float* Wfc  = (const float*)d_in[15];
    const float* bfc  = (const float*)d_in[16];
    const float* Whg  = (const float*)d_in[17];
    const float* bhg  = (const float*)d_in[18];
    const float* Wc   = (const float*)d_in[19];
    const float* bc   = (const float*)d_in[20];
    const float* Wv   = (const float*)d_in[21];
    const float* bv   = (const float*)d_in[22];
    const float* Wq   = (const float*)d_in[23];
    const float* bq   = (const float*)d_in[24];
    const float* h_mat  = (const float*)d_in[25];
    const float* h_bias = (const float*)d_in[26];
    const float* gamma  = (const float*)d_in[27];
    const float* beta   = (const float*)d_in[28];
    const int*   trip   = (const int*)d_in[29];
    const int*   ei     = (const int*)d_in[30];

    int N  = in_sizes[29] / 4;
    int E  = in_sizes[30] / 2;
    int CF = in_sizes[19] / 128;
    int B  = in_sizes[0] / CF;
    int H1 = in_sizes[4] / 128;   // 4
    int H2 = in_sizes[10] / 128;  // 5
    int HOUT = in_sizes[26];
    if (N > NMAX) N = NMAX;
    if (E > EMAX) E = EMAX;
    float* out = (float*)d_out;

    void *ph1;
    void *pA2h, *pA2l, *pA3h, *pA3l;
    void *pb1h, *pb1l, *pb2h, *pb2l, *pb3h, *pb3l;
    cudaGetSymbolAddress(&ph1,  g_h1);
    cudaGetSymbolAddress(&pA2h, g_A2h);
    cudaGetSymbolAddress(&pA2l, g_A2l);
    cudaGetSymbolAddress(&pA3h, g_A3h);
    cudaGetSymbolAddress(&pA3l, g_A3l);
    cudaGetSymbolAddress(&pb1h, g_bt1h);
    cudaGetSymbolAddress(&pb1l, g_bt1l);
    cudaGetSymbolAddress(&pb2h, g_bt2h);
    cudaGetSymbolAddress(&pb2l, g_bt2l);
    cudaGetSymbolAddress(&pb3h, g_bt3h);
    cudaGetSymbolAddress(&pb3l, g_bt3l);

    cudaFuncSetAttribute(tgemm,    cudaFuncAttributeMaxDynamicSharedMemorySize, 49152);
    cudaFuncSetAttribute(tgemm_r4, cudaFuncAttributeMaxDynamicSharedMemorySize, 49152);

    int M1 = H1 * CDIM;  // 512
    int M2 = H2 * CDIM;  // 640
    int mt = (N + 63) / 64;

    // ---- prep ----
    int s0 = (N + 255) / 256;
    int s1 = (128 * M1 + 255) / 256;
    int s2 = (128 * 128 * H2 + 255) / 256;
    int s3 = (128 * M2 + 255) / 256;
    int s4 = (M1 + 255) / 256;
    int s5 = (CDIM * 2 * H2 + 255) / 256;
    prep_kernel<<<s0 + s1 + s2 + s3 + s4 + s5, 256>>>(Wl1, W2, Wl2, Wd, bd, W1,
                                                      a2s, a2d,
                                                      N, M1, M2, H2, s0, s1, s2, s3, s4);

    // ---- combined: count + es1 + q-precompute ----
    int c0 = (E / 8 + 255) / 256;
    int c1 = (N + 255) / 256;
    cnt_es1_q_kernel<<<c0 + c1 + B, 256>>>(ei, E, trip, a1s, a1d, N, M1,
                                           cell, Wc, bc, Wq, bq, CF, c0, c1);

    scan_kernel<<<1, 1024>>>(N);
    fill_kernel<<<(E / 8 + 255) / 256, 256>>>(ei, E);

    // ---- GAT layer 1 ----
    agg_rank4_kernel<<<(N * 32 + 255) / 256, 256>>>(trip, N);
    tgemm_r4<<<dim3(1, mt, 1), 256, 49152>>>(
        b1, (const __nv_bfloat16*)pb1h, (const __nv_bfloat16*)pb1l,
        (float*)ph1, N, bl1);

    // ---- GAT layer 2 ----
    es2_kernel<<<(N + 7) / 8, 256>>>(N, H2);
    agg2_kernel<<<(N * 32 + 255) / 256, 256>>>((const float*)ph1, N);
    tgemm<<<dim3(1, mt, H2), 256, 49152>>>(
        (const __nv_bfloat16*)pA2h, (const __nv_bfloat16*)pA2l, M2, 128,
        (const __nv_bfloat16*)pb2h, (const __nv_bfloat16*)pb2l, 128 * 128,
        nullptr, (__nv_bfloat16*)pA3h, (__nv_bfloat16*)pA3l, M2, 128,
        N, 128, b2, 128, 1);
    tgemm<<<dim3(1, mt, 1), 256, 49152>>>(
        (const __nv_bfloat16*)pA3h, (const __nv_bfloat16*)pA3l, M2, 0,
        (const __nv_bfloat16*)pb3h, (const __nv_bfloat16*)pb3l, 0,
        nullptr, nullptr, nullptr, CDIM, 0, N, M2, bl2, 0, 0);

    // ---- tail (R13 structure) ----
    tail0_kernel<<<1, 384>>>(Wfc, bfc, Whg, bhg, Wv, bv, h_mat, h_bias, N, HOUT);
    tail1_kernel<<<B, 128>>>(B);
    tail2_kernel<<<(B * 128 + 255) / 256, 256>>>(gamma, beta, out, B);
}

// round 17
// speedup vs baseline: 1.0800x; 1.0099x over previous
#include <cuda_runtime.h>
#include <cuda_bf16.h>
#include <math.h>
#include <stdint.h>

#define NMAX 20000
#define EMAX 500000
#define CDIM 128
#define NPAD (NMAX + 128)

// ---------------------------------------------------------------------------
// Static device scratch
// ---------------------------------------------------------------------------
__device__ float g_h1  [NMAX * CDIM];
__device__ float g_es  [NMAX * 4];
__device__ float g_ed  [NMAX * 4];
__device__ float g_es2p[NMAX * 8];
__device__ float g_ed2p[NMAX * 8];
__device__ float g_tt  [NMAX * 16];
__device__ int   g_cnt   [NMAX];
__device__ int   g_rowptr[NMAX + 1];
__device__ int   g_cursor[NMAX];
__device__ int   g_csrc  [EMAX];
__device__ float g_hsum  [CDIM];
__device__ float g_small [1024];
__device__ float g_logits[256 * CDIM];
__device__ float g_qrow  [256 * 384];
__device__ float g_bn1   [CDIM];
__device__ float g_bn2   [CDIM];
// order-preserving encoded per-head logit maxima:
// [0..3] es1, [4..7] ed1, [8..12] es2, [13..17] ed2
__device__ unsigned g_emax[32];
__device__ float g_Wp  [4 * 512];
__device__ float g_bp  [512];
__device__ float g_fold2[128 * 10];
__device__ __nv_bfloat16 g_A2h[NPAD * 640], g_A2l[NPAD * 640];
__device__ __nv_bfloat16 g_A3h[NPAD * 640], g_A3l[NPAD * 640];
__device__ __nv_bfloat16 g_bt1h[128 * 512], g_bt1l[128 * 512];
__device__ __nv_bfloat16 g_bt2h[5 * 128 * 128], g_bt2l[5 * 128 * 128];
__device__ __nv_bfloat16 g_bt3h[128 * 640], g_bt3l[128 * 640];

// ---------------------------------------------------------------------------
// helpers
// ---------------------------------------------------------------------------
__device__ __forceinline__ uint32_t smem_u32(const void* p) {
    uint32_t a;
    asm("{ .reg .u64 t; cvta.to.shared.u64 t, %1; cvt.u32.u64 %0, t; }" : "=r"(a) : "l"(p));
    return a;
}
__device__ __forceinline__ void ldsm4(uint32_t* r, uint32_t addr) {
    asm volatile("ldmatrix.sync.aligned.m8n8.x4.shared.b16 {%0,%1,%2,%3}, [%4];"
                 : "=r"(r[0]), "=r"(r[1]), "=r"(r[2]), "=r"(r[3]) : "r"(addr));
}
__device__ __forceinline__ void mma16816(float* d, const uint32_t* a, const uint32_t* b) {
    asm volatile(
        "mma.sync.aligned.m16n8k16.row.col.f32.bf16.bf16.f32 "
        "{%0,%1,%2,%3}, {%4,%5,%6,%7}, {%8,%9}, {%0,%1,%2,%3};"
        : "+f"(d[0]), "+f"(d[1]), "+f"(d[2]), "+f"(d[3])
        : "r"(a[0]), "r"(a[1]), "r"(a[2]), "r"(a[3]), "r"(b[0]), "r"(b[1]));
}
__device__ __forceinline__ uint32_t pack_bf(__nv_bfloat16 a, __nv_bfloat16 b) {
    __nv_bfloat162 t;
    t.x = a; t.y = b;
    return *reinterpret_cast<uint32_t*>(&t);
}
__device__ __forceinline__ unsigned fenc(float v) {
    unsigned u = __float_as_uint(v);
    return (u & 0x80000000u) ? ~u : (u | 0x80000000u);
}
__device__ __forceinline__ float fdec(unsigned k) {
    unsigned u = (k & 0x80000000u) ? (k & 0x7FFFFFFFu) : ~k;
    return __uint_as_float(u);
}
#define CPA(dst, src) \
    asm volatile("cp.async.cg.shared.global [%0], [%1], 16;" :: "r"(dst), "l"(src))

// ---------------------------------------------------------------------------
// prep: zero + 3x weight split + drug-linear fold + wfold2 (one launch)
// ---------------------------------------------------------------------------
__global__ void prep_kernel(const float* __restrict__ Wl1, const float* __restrict__ W2,
                            const float* __restrict__ Wl2, const float* __restrict__ Wd,
                            const float* __restrict__ bd,  const float* __restrict__ W1,
                            const float* __restrict__ a2s, const float* __restrict__ a2d,
                            int N, int M1, int M2, int H2,
                            int s0, int s1, int s2, int s3, int s4) {
    int b = blockIdx.x, tid = threadIdx.x;
    if (b < s0) {
        int i = b * 256 + tid;
        if (i < N) g_cnt[i] = 0;
        if (b == 0 && tid < CDIM) { g_hsum[tid] = 0.f; g_bn1[tid] = 0.f; g_bn2[tid] = 0.f; }
        if (b == 0 && tid < 32) g_emax[tid] = 0u;
        return;
    }
    b -= s0;
    if (b < s1) {
        int idx = b * 256 + tid;
        if (idx < 128 * M1) {
            int j = idx / M1, k = idx - j * M1;
            float v = Wl1[(size_t)k * 128 + j];
            __nv_bfloat16 h = __float2bfloat16(v);
            g_bt1h[idx] = h;
            g_bt1l[idx] = __float2bfloat16(v - __bfloat162float(h));
        }
        return;
    }
    b -= s1;
    if (b < s2) {
        int idx = b * 256 + tid;
        if (idx < 128 * 128 * H2) {
            int z = idx / 16384, r = idx - z * 16384;
            int j = r / 128, k = r - j * 128;
            float v = W2[(size_t)k * M2 + z * 128 + j];
            __nv_bfloat16 h = __float2bfloat16(v);
            g_bt2h[idx] = h;
            g_bt2l[idx] = __float2bfloat16(v - __bfloat162float(h));
        }
        return;
    }
    b -= s2;
    if (b < s3) {
        int idx = b * 256 + tid;
        if (idx < 128 * M2) {
            int j = idx / M2, k = idx - j * M2;
            float v = Wl2[(size_t)k * 128 + j];
            __nv_bfloat16 h = __float2bfloat16(v);
            g_bt3h[idx] = h;
            g_bt3l[idx] = __float2bfloat16(v - __bfloat162float(h));
        }
        return;
    }
    b -= s3;
    if (b < s4) {
        int j = b * 256 + tid;
        if (j < M1) {
            float a0 = 0.f, a1 = 0.f, a2 = 0.f, a3 = 0.f, ab = 0.f;
#pragma unroll 4
            for (int k = 0; k < CDIM; k++) {
                float w = W1[k * M1 + j];
                a0 += Wd[0 * CDIM + k] * w;
                a1 += Wd[1 * CDIM + k] * w;
                a2 += Wd[2 * CDIM + k] * w;
                a3 += Wd[3 * CDIM + k] * w;
                ab += bd[k] * w;
            }
            g_Wp[0 * M1 + j] = a0;
            g_Wp[1 * M1 + j] = a1;
            g_Wp[2 * M1 + j] = a2;
            g_Wp[3 * M1 + j] = a3;
            g_bp[j] = ab;
        }
        return;
    }
    b -= s4;
    {
        int idx = b * 256 + tid;
        if (idx < CDIM * 2 * H2) {
            int c = idx / (2 * H2), o = idx - c * (2 * H2);
            int h = o % H2;
            const float* av = (o < H2) ? a2s : a2d;
            float s = 0.f;
            for (int k = 0; k < CDIM; k++) s += W2[c * M2 + h * CDIM + k] * av[h * CDIM + k];
            g_fold2[c * (2 * H2) + o] = s;
        }
    }
}

// ---------------------------------------------------------------------------
// combined: edge count (2 edges/thread) + layer-1 logits (+ global maxima)
// + q-precompute
// ---------------------------------------------------------------------------
__global__ void cnt_es1_q_kernel(const int* __restrict__ ei, int E,
                                 const int* __restrict__ trip,
                                 const float* __restrict__ a1s,
                                 const float* __restrict__ a1d, int N, int M1,
                                 const float* __restrict__ cell,
                                 const float* __restrict__ Wc, const float* __restrict__ bc,
                                 const float* __restrict__ Wq, const float* __restrict__ bq,
                                 int CF,
                                 int c0, int c1) {
    __shared__ float sm[1024];
    __shared__ float crow[128];
    __shared__ unsigned smax[8];
    int b = blockIdx.x, tid = threadIdx.x;
    if (b < c0) {                       // count (2 edges/thread)
        int e = (b * 256 + tid) * 2;
        if (e + 1 < E) {
            int2 s = *(const int2*)(ei + e);
            int2 d = *(const int2*)(ei + E + e);
            if (s.x != d.x) atomicAdd(&g_cnt[d.x], 1);
            if (s.y != d.y) atomicAdd(&g_cnt[d.y], 1);
        } else if (e < E) {
            int s = ei[e], d = ei[E + e];
            if (s != d) atomicAdd(&g_cnt[d], 1);
        }
        return;
    }
    b -= c0;
    if (b < c1) {                       // es1 (+ per-head global max)
        float* f1 = sm;
        if (tid < 16) {
            int h = tid >> 2, i = tid & 3;
            float s = 0.f;
            for (int k = 0; k < CDIM; k++) s += g_Wp[i * M1 + h * CDIM + k] * a1s[h * CDIM + k];
            f1[tid] = s;
        } else if (tid < 32) {
            int t = tid - 16;
            int h = t >> 2, i = t & 3;
            float s = 0.f;
            for (int k = 0; k < CDIM; k++) s += g_Wp[i * M1 + h * CDIM + k] * a1d[h * CDIM + k];
            f1[tid] = s;
        } else if (tid < 36) {
            int h = tid - 32;
            float s = 0.f;
            for (int k = 0; k < CDIM; k++) s += g_bp[h * CDIM + k] * a1s[h * CDIM + k];
            f1[tid] = s;
        } else if (tid < 40) {
            int h = tid - 36;
            float s = 0.f;
            for (int k = 0; k < CDIM; k++) s += g_bp[h * CDIM + k] * a1d[h * CDIM + k];
            f1[tid] = s;
        }
        if (tid >= 64 && tid < 72) smax[tid - 64] = 0u;
        __syncthreads();
        int n = b * 256 + tid;
        bool valid = (n < N);
        float esv[4], edv[4];
        if (valid) {
            int4 tv = *(const int4*)(trip + n * 4);
            float t0 = (float)tv.x, t1 = (float)tv.y, t2 = (float)tv.z, t3 = (float)tv.w;
#pragma unroll
            for (int h = 0; h < 4; h++) {
                esv[h] = f1[32 + h] + t0 * f1[h * 4 + 0] + t1 * f1[h * 4 + 1]
                       + t2 * f1[h * 4 + 2] + t3 * f1[h * 4 + 3];
                edv[h] = f1[36 + h] + t0 * f1[16 + h * 4 + 0] + t1 * f1[16 + h * 4 + 1]
                       + t2 * f1[16 + h * 4 + 2] + t3 * f1[16 + h * 4 + 3];
            }
        } else {
#pragma unroll
            for (int h = 0; h < 4; h++) { esv[h] = -1e30f; edv[h] = -1e30f; }
        }
        // warp max reduction per head
        float wm[8];
#pragma unroll
        for (int h = 0; h < 4; h++) { wm[h] = esv[h]; wm[4 + h] = edv[h]; }
#pragma unroll
        for (int h = 0; h < 8; h++)
            for (int o = 16; o; o >>= 1)
                wm[h] = fmaxf(wm[h], __shfl_xor_sync(0xffffffffu, wm[h], o));
        if ((tid & 31) < 8) atomicMax(&smax[tid & 31], fenc(wm[tid & 31]));
        if (valid) {
            *(float4*)(g_es + n * 4) = make_float4(esv[0], esv[1], esv[2], esv[3]);
            *(float4*)(g_ed + n * 4) = make_float4(edv[0], edv[1], edv[2], edv[3]);
        }
        __syncthreads();
        if (tid < 8) atomicMax(&g_emax[tid], smax[tid]);
        return;
    }
    b -= c1;
    {                                   // q precompute for batch row b
        for (int i = tid; i < CF; i += 256) sm[i] = cell[(size_t)b * CF + i];
        __syncthreads();
        if (tid < 128) {
            float a = bc[tid];
            for (int k = 0; k < CF; k++) a += sm[k] * Wc[k * 128 + tid];
            crow[tid] = a > 0.f ? a : 0.f;
        }
        __syncthreads();
        for (int mI = tid; mI < 384; mI += 256) {
            float q = bq[mI];
            for (int k = 0; k < 128; k++) q += crow[k] * Wq[k * 384 + mI];
            g_qrow[b * 384 + mI] = q > 0.f ? q : 0.f;
        }
    }
}

// ---------------------------------------------------------------------------
// scan (vectorized single block, 1024 threads)
// ---------------------------------------------------------------------------
__global__ void scan_kernel(int N) {
    __shared__ int wsum[32];
    __shared__ int carry_s;
    int tid = threadIdx.x, lane = tid & 31, wid = tid >> 5;
    if (tid == 0) { carry_s = 0; g_rowptr[0] = 0; }
    __syncthreads();
    int NT = (N + 3) >> 2;
    for (int base = 0; base < NT; base += 1024) {
        int i4 = base + tid;
        int b0 = i4 * 4;
        int4 v = make_int4(0, 0, 0, 0);
        if (b0 + 3 < N) {
            v = *(const int4*)(g_cnt + b0);
        } else if (b0 < N) {
            v.x = g_cnt[b0];
            if (b0 + 1 < N) v.y = g_cnt[b0 + 1];
            if (b0 + 2 < N) v.z = g_cnt[b0 + 2];
        }
        int p1 = v.x, p2 = p1 + v.y, p3 = p2 + v.z, p4 = p3 + v.w;
        int x = p4;
#pragma unroll
        for (int o = 1; o < 32; o <<= 1) {
            int t = __shfl_up_sync(0xffffffffu, x, o);
            if (lane >= o) x += t;
        }
        if (lane == 31) wsum[wid] = x;
        __syncthreads();
        if (wid == 0) {
            int s = wsum[lane];
#pragma unroll
            for (int o = 1; o < 32; o <<= 1) {
                int t = __shfl_up_sync(0xffffffffu, s, o);
                if (lane >= o) s += t;
            }
            wsum[lane] = s;
        }
        __syncthreads();
        int pre = carry_s + (wid ? wsum[wid - 1] : 0) + (x - p4);
        if (b0 < N)     { g_rowptr[b0 + 1] = pre + p1; g_cursor[b0]     = pre; }
        if (b0 + 1 < N) { g_rowptr[b0 + 2] = pre + p2; g_cursor[b0 + 1] = pre + p1; }
        if (b0 + 2 < N) { g_rowptr[b0 + 3] = pre + p3; g_cursor[b0 + 2] = pre + p2; }
        if (b0 + 3 < N) { g_rowptr[b0 + 4] = pre + p4; g_cursor[b0 + 3] = pre + p3; }
        __syncthreads();
        if (tid == 0) carry_s += wsum[31];
        __syncthreads();
    }
}

// fill (2 edges/thread)
__global__ void fill_kernel(const int* __restrict__ ei, int E) {
    int e = (blockIdx.x * blockDim.x + threadIdx.x) * 2;
    if (e + 1 < E) {
        int2 s = *(const int2*)(ei + e);
        int2 d = *(const int2*)(ei + E + e);
        if (s.x != d.x) { int p = atomicAdd(&g_cursor[d.x], 1); g_csrc[p] = s.x; }
        if (s.y != d.y) { int p = atomicAdd(&g_cursor[d.y], 1); g_csrc[p] = s.y; }
    } else if (e < E) {
        int s = ei[e], d = ei[E + e];
        if (s != d) { int p = atomicAdd(&g_cursor[d], 1); g_csrc[p] = s; }
    }
}

// ---------------------------------------------------------------------------
// Layer-1 aggregation (single pass; global upper-bound max)
// ---------------------------------------------------------------------------
__global__ void agg_rank4_kernel(const int* __restrict__ trip, int N) {
    const int H = 4;
    int warp = (blockIdx.x * blockDim.x + threadIdx.x) >> 5;
    int lane = threadIdx.x & 31;
    if (warp >= N) return;
    int n   = warp;
    int r0  = g_rowptr[n];
    int deg = g_rowptr[n + 1] - r0;
    int tot = deg + 1;

    float4 edv4 = *(const float4*)(g_ed + n * 4);
    float edv[H] = {edv4.x, edv4.y, edv4.z, edv4.w};
    float m[H];
#pragma unroll
    for (int h = 0; h < H; h++) {
        float e = fdec(g_emax[h]) + fdec(g_emax[4 + h]);
        m[h] = e > 0.f ? e : 0.2f * e;
    }
    float4 acc[H];
    float z[H];
#pragma unroll
    for (int h = 0; h < H; h++) { acc[h] = make_float4(0.f, 0.f, 0.f, 0.f); z[h] = 0.f; }
    for (int i = lane; i < tot; i += 32) {
        int src = (i < deg) ? g_csrc[r0 + i] : n;
        float4 es = *(const float4*)(g_es + src * 4);
        float ev[H] = {es.x, es.y, es.z, es.w};
        int4 tv = *(const int4*)(trip + src * 4);
        float4 tf = make_float4((float)tv.x, (float)tv.y, (float)tv.z, (float)tv.w);
#pragma unroll
        for (int h = 0; h < H; h++) {
            float e = ev[h] + edv[h];
            e = e > 0.f ? e : 0.2f * e;
            float w = __expf(e - m[h]);
            z[h] += w;
            acc[h].x += w * tf.x; acc[h].y += w * tf.y;
            acc[h].z += w * tf.z; acc[h].w += w * tf.w;
        }
    }
#pragma unroll
    for (int h = 0; h < H; h++) {
        for (int o = 16; o; o >>= 1) {
            acc[h].x += __shfl_xor_sync(0xffffffffu, acc[h].x, o);
            acc[h].y += __shfl_xor_sync(0xffffffffu, acc[h].y, o);
            acc[h].z += __shfl_xor_sync(0xffffffffu, acc[h].z, o);
            acc[h].w += __shfl_xor_sync(0xffffffffu, acc[h].w, o);
            z[h]     += __shfl_xor_sync(0xffffffffu, z[h], o);
        }
    }
    if (lane == 0) {
#pragma unroll
        for (int h = 0; h < H; h++) {
            float iz = 1.f / z[h];
            float4 r = make_float4(acc[h].x * iz, acc[h].y * iz, acc[h].z * iz, acc[h].w * iz);
            *(float4*)(g_tt + n * 16 + h * 4) = r;
        }
    }
}

// ---------------------------------------------------------------------------
// tgemm_r4: 64-row tile, 2-stage, 3 CTA/SM, colsum epilogue
// smem: A 2x8KB @0, B 2x16KB @16384 -> 49152 B.
// ---------------------------------------------------------------------------
__global__ void __launch_bounds__(256, 3)
tgemm_r4(const float* __restrict__ b1,
         const __nv_bfloat16* __restrict__ Bh, const __nv_bfloat16* __restrict__ Bl,
         float* __restrict__ Cf, int M, const float* __restrict__ cbias) {
    const int K = 512;
    extern __shared__ __align__(16) char dsm[];
    char*    sAc = dsm;
    uint32_t sAu = smem_u32(dsm);
    uint32_t sBu = sAu + 16384;

    int tid  = threadIdx.x;
    int wid  = tid >> 5;
    int lane = tid & 31;
    int m0   = blockIdx.y * 64;
    int wm   = wid & 1;
    int wn   = wid >> 1;

    float acc[2][4][4];
#pragma unroll
    for (int i = 0; i < 2; i++)
#pragma unroll
        for (int j = 0; j < 4; j++)
#pragma unroll
            for (int l = 0; l < 4; l++) acc[i][j][l] = 0.f;

#define STAGEB(BUF, KC)                                                        \
    {                                                                          \
        int _kc = (KC);                                                        \
        _Pragma("unroll")                                                      \
        for (int it = 0; it < 4; it++) {                                       \
            int idx = it * 256 + tid;                                          \
            int row = idx >> 3, ch = idx & 7;                                  \
            const __nv_bfloat16* gs = ((ch < 4) ? Bh : Bl)                     \
                + (size_t)row * K + _kc + (ch & 3) * 8;                        \
            uint32_t dst = sBu + (BUF) * 16384 + row * 128                     \
                + ((ch ^ (row & 7)) << 4);                                     \
            CPA(dst, gs);                                                      \
        }                                                                      \
    }

#define STAGEA(BUF, KC)                                                        \
    {                                                                          \
        int _kc = (KC);                                                        \
        int _h  = _kc >> 7;                                                    \
        _Pragma("unroll")                                                      \
        for (int it = 0; it < 2; it++) {                                       \
            int idx = it * 256 + tid;                                          \
            int row = idx >> 3, cg = idx & 7;                                  \
            int gr = m0 + row; if (gr >= M) gr = M - 1;                        \
            float4 t = *(const float4*)(g_tt + gr * 16 + _h * 4);              \
            int j = _kc + cg * 4;                                              \
            float4 w0 = *(const float4*)(g_Wp + 0 * 512 + j);                  \
            float4 w1 = *(const float4*)(g_Wp + 1 * 512 + j);                  \
            float4 w2 = *(const float4*)(g_Wp + 2 * 512 + j);                  \
            float4 w3 = *(const float4*)(g_Wp + 3 * 512 + j);                  \
            float4 bb = *(const float4*)(g_bp + j);                            \
            float4 b2v = *(const float4*)(b1 + j);                             \
            float v0 = bb.x + b2v.x + t.x * w0.x + t.y * w1.x + t.z * w2.x + t.w * w3.x; \
            float v1 = bb.y + b2v.y + t.x * w0.y + t.y * w1.y + t.z * w2.y + t.w * w3.y; \
            float v2 = bb.z + b2v.z + t.x * w0.z + t.y * w1.z + t.z * w2.z + t.w * w3.z; \
            float v3 = bb.w + b2v.w + t.x * w0.w + t.y * w1.w + t.z * w2.w + t.w * w3.w; \
            v0 = v0 > 0.f ? v0 : __expf(v0) - 1.f;                             \
            v1 = v1 > 0.f ? v1 : __expf(v1) - 1.f;                             \
            v2 = v2 > 0.f ? v2 : __expf(v2) - 1.f;                             \
            v3 = v3 > 0.f ? v3 : __expf(v3) - 1.f;                             \
            __nv_bfloat16 h0 = __float2bfloat16(v0);                           \
            __nv_bfloat16 h1 = __float2bfloat16(v1);                           \
            __nv_bfloat16 h2 = __float2bfloat16(v2);                           \
            __nv_bfloat16 h3 = __float2bfloat16(v3);                           \
            uint2 hi2 = make_uint2(pack_bf(h0, h1), pack_bf(h2, h3));          \
            uint2 lo2 = make_uint2(                                            \
                pack_bf(__float2bfloat16(v0 - __bfloat162float(h0)),           \
                        __float2bfloat16(v1 - __bfloat162float(h1))),          \
                pack_bf(__float2bfloat16(v2 - __bfloat162float(h2)),           \
                        __float2bfloat16(v3 - __bfloat162float(h3))));         \
            int ch = cg >> 1, rem = (cg & 1) * 8;                              \
            char* base = sAc + (BUF) * 8192 + row * 128;                       \
            *(uint2*)(base + (((ch)     ^ (row & 7)) << 4) + rem) = hi2;       \
            *(uint2*)(base + (((ch + 4) ^ (row & 7)) << 4) + rem) = lo2;       \
        }                                                                      \
    }

    int nk = K >> 5;
    STAGEB(0, 0)
    asm volatile("cp.async.commit_group;");
    STAGEA(0, 0)

    for (int i = 0; i < nk; i++) {
        int buf = i & 1;
        if (i + 1 < nk) {
            STAGEB(buf ^ 1, (i + 1) * 32)
            asm volatile("cp.async.commit_group;");
            STAGEA(buf ^ 1, (i + 1) * 32)
            asm volatile("cp.async.wait_group 1;");
        } else {
            asm volatile("cp.async.wait_group 0;");
        }
        __syncthreads();

        uint32_t a_base = sAu + buf * 8192;
        uint32_t b_base = sBu + buf * 16384;
#pragma unroll
        for (int ks = 0; ks < 2; ks++) {
            uint32_t ah[2][4], al[2][4], bh[2][4], bl[2][4];
            int arow = (lane & 7) + ((lane >> 3) & 1) * 8;
            int akg  = 2 * ks + (lane >> 4);
#pragma unroll
            for (int mf = 0; mf < 2; mf++) {
                int r = 32 * wm + 16 * mf + arow;
                ldsm4(ah[mf], a_base + r * 128 + (((akg)     ^ (r & 7)) << 4));
                ldsm4(al[mf], a_base + r * 128 + (((akg + 4) ^ (r & 7)) << 4));
            }
            int brow = (lane & 7) + (lane >> 4) * 8;
            int bkg  = 2 * ks + ((lane >> 3) & 1);
#pragma unroll
            for (int q = 0; q < 2; q++) {
                int r = 32 * wn + 16 * q + brow;
                ldsm4(bh[q], b_base + r * 128 + (((bkg)     ^ (r & 7)) << 4));
                ldsm4(bl[q], b_base + r * 128 + (((bkg + 4) ^ (r & 7)) << 4));
            }
#pragma unroll
            for (int mf = 0; mf < 2; mf++) {
#pragma unroll
                for (int q = 0; q < 2; q++) {
                    mma16816(acc[mf][2 * q + 0], ah[mf], &bh[q][0]);
                    mma16816(acc[mf][2 * q + 1], ah[mf], &bh[q][2]);
                    mma16816(acc[mf][2 * q + 0], al[mf], &bh[q][0]);
                    mma16816(acc[mf][2 * q + 1], al[mf], &bh[q][2]);
                    mma16816(acc[mf][2 * q + 0], ah[mf], &bl[q][0]);
                    mma16816(acc[mf][2 * q + 1], ah[mf], &bl[q][2]);
                }
            }
        }
        __syncthreads();
    }
#undef STAGEA
#undef STAGEB

    float* colsum = (float*)dsm;
    if (tid < 128) colsum[tid] = 0.f;
    __syncthreads();
#pragma unroll
    for (int mf = 0; mf < 2; mf++) {
        int r0 = m0 + 32 * wm + 16 * mf + (lane >> 2);
#pragma unroll
        for (int nf = 0; nf < 4; nf++) {
            int col = 32 * wn + 8 * nf + 2 * (lane & 3);
            float cb0 = cbias[col], cb1 = cbias[col + 1];
            float s0 = 0.f, s1 = 0.f;
#pragma unroll
            for (int rr = 0; rr < 2; rr++) {
                int r = r0 + rr * 8;
                if (r >= M) continue;
                float v0 = acc[mf][nf][2 * rr + 0] + cb0;
                float v1 = acc[mf][nf][2 * rr + 1] + cb1;
                *(float2*)(Cf + (size_t)r * CDIM + col) = make_float2(v0, v1);
                s0 += v0; s1 += v1;
            }
            atomicAdd(&colsum[col], s0);
            atomicAdd(&colsum[col + 1], s1);
        }
    }
    __syncthreads();
    if (tid < 128) atomicAdd(&g_hsum[tid], colsum[tid]);
}

// ---------------------------------------------------------------------------
// generic tgemm: 64-row tile, 2-stage, 3 CTA/SM
// smem: A 2x8KB @0, B 2x16KB @16384 -> 49152 B.
// ---------------------------------------------------------------------------
__global__ void __launch_bounds__(256, 3)
tgemm(const __nv_bfloat16* __restrict__ Ah, const __nv_bfloat16* __restrict__ Al,
      int lda, int boa,
      const __nv_bfloat16* __restrict__ Bh, const __nv_bfloat16* __restrict__ Bl, int bob,
      float* __restrict__ Cf, __nv_bfloat16* __restrict__ Ch, __nv_bfloat16* __restrict__ Cl,
      int ldc, int boc,
      int M, int K, const float* __restrict__ cbias, int bocb, int celu) {
    Ah += (size_t)blockIdx.z * boa;
    Al += (size_t)blockIdx.z * boa;
    Bh += (size_t)blockIdx.z * bob;
    Bl += (size_t)blockIdx.z * bob;
    if (Cf) Cf += (size_t)blockIdx.z * boc;
    if (Ch) { Ch += (size_t)blockIdx.z * boc; Cl += (size_t)blockIdx.z * boc; }
    cbias += (size_t)blockIdx.z * bocb;
    int sum_only = (Cf == nullptr) && (Ch == nullptr);

    extern __shared__ __align__(16) char dsm[];
    uint32_t sAu = smem_u32(dsm);
    uint32_t sBu = sAu + 16384;

    int tid  = threadIdx.x;
    int wid  = tid >> 5;
    int lane = tid & 31;
    int m0   = blockIdx.y * 64;
    int wm   = wid & 1;
    int wn   = wid >> 1;

    float acc[2][4][4];
#pragma unroll
    for (int i = 0; i < 2; i++)
#pragma unroll
        for (int j = 0; j < 4; j++)
#pragma unroll
            for (int l = 0; l < 4; l++) acc[i][j][l] = 0.f;

#define STAGE(BUF, KC)                                                         \
    {                                                                          \
        int _kc = (KC);                                                        \
        _Pragma("unroll")                                                      \
        for (int it = 0; it < 2; it++) {                                       \
            int idx = it * 256 + tid;                                          \
            int row = idx >> 3, ch = idx & 7;                                  \
            const __nv_bfloat16* gs = ((ch < 4) ? Ah : Al)                     \
                + (size_t)(m0 + row) * lda + _kc + (ch & 3) * 8;               \
            uint32_t dst = sAu + (BUF) * 8192 + row * 128                      \
                + ((ch ^ (row & 7)) << 4);                                     \
            CPA(dst, gs);                                                      \
        }                                                                      \
        _Pragma("unroll")                                                      \
        for (int it = 0; it < 4; it++) {                                       \
            int idx = it * 256 + tid;                                          \
            int row = idx >> 3, ch = idx & 7;                                  \
            const __nv_bfloat16* gs = ((ch < 4) ? Bh : Bl)                     \
                + (size_t)row * K + _kc + (ch & 3) * 8;                        \
            uint32_t dst = sBu + (BUF) * 16384 + row * 128                     \
                + ((ch ^ (row & 7)) << 4);                                     \
            CPA(dst, gs);                                                      \
        }                                                                      \
    }

    int nk = K >> 5;
    STAGE(0, 0)
    asm volatile("cp.async.commit_group;");

    for (int i = 0; i < nk; i++) {
        int buf = i & 1;
        if (i + 1 < nk) {
            STAGE(buf ^ 1, (i + 1) * 32)
            asm volatile("cp.async.commit_group;");
            asm volatile("cp.async.wait_group 1;");
        } else {
            asm volatile("cp.async.wait_group 0;");
        }
        __syncthreads();

        uint32_t a_base = sAu + buf * 8192;
        uint32_t b_base = sBu + buf * 16384;
#pragma unroll
        for (int ks = 0; ks < 2; ks++) {
            uint32_t ah[2][4], al[2][4], bh[2][4], bl[2][4];
            int arow = (lane & 7) + ((lane >> 3) & 1) * 8;
            int akg  = 2 * ks + (lane >> 4);
#pragma unroll
            for (int mf = 0; mf < 2; mf++) {
                int r = 32 * wm + 16 * mf + arow;
                ldsm4(ah[mf], a_base + r * 128 + (((akg)     ^ (r & 7)) << 4));
                ldsm4(al[mf], a_base + r * 128 + (((akg + 4) ^ (r & 7)) << 4));
            }
            int brow = (lane & 7) + (lane >> 4) * 8;
            int bkg  = 2 * ks + ((lane >> 3) & 1);
#pragma unroll
            for (int q = 0; q < 2; q++) {
                int r = 32 * wn + 16 * q + brow;
                ldsm4(bh[q], b_base + r * 128 + (((bkg)     ^ (r & 7)) << 4));
                ldsm4(bl[q], b_base + r * 128 + (((bkg + 4) ^ (r & 7)) << 4));
            }
#pragma unroll
            for (int mf = 0; mf < 2; mf++) {
#pragma unroll
                for (int q = 0; q < 2; q++) {
                    mma16816(acc[mf][2 * q + 0], ah[mf], &bh[q][0]);
                    mma16816(acc[mf][2 * q + 1], ah[mf], &bh[q][2]);
                    mma16816(acc[mf][2 * q + 0], al[mf], &bh[q][0]);
                    mma16816(acc[mf][2 * q + 1], al[mf], &bh[q][2]);
                    mma16816(acc[mf][2 * q + 0], ah[mf], &bl[q][0]);
                    mma16816(acc[mf][2 * q + 1], ah[mf], &bl[q][2]);
                }
            }
        }
        __syncthreads();
    }
#undef STAGE

    float* colsum = (float*)dsm;
    if (sum_only) {
        if (tid < 128) colsum[tid] = 0.f;
        __syncthreads();
    }
#pragma unroll
    for (int mf = 0; mf < 2; mf++) {
        int r0 = m0 + 32 * wm + 16 * mf + (lane >> 2);
#pragma unroll
        for (int nf = 0; nf < 4; nf++) {
            int col = 32 * wn + 8 * nf + 2 * (lane & 3);
            float cb0 = cbias[col], cb1 = cbias[col + 1];
            float s0 = 0.f, s1 = 0.f;
#pragma unroll
            for (int rr = 0; rr < 2; rr++) {
                int r = r0 + rr * 8;
                if (r >= M) continue;
                float v0 = acc[mf][nf][2 * rr + 0] + cb0;
                float v1 = acc[mf][nf][2 * rr + 1] + cb1;
                if (Cf) {
                    *(float2*)(Cf + (size_t)r * ldc + col) = make_float2(v0, v1);
                } else if (Ch) {
                    if (celu) {
                        v0 = v0 > 0.f ? v0 : __expf(v0) - 1.f;
                        v1 = v1 > 0.f ? v1 : __expf(v1) - 1.f;
                    }
                    __nv_bfloat16 h0 = __float2bfloat16(v0);
                    __nv_bfloat16 h1 = __float2bfloat16(v1);
                    size_t o = (size_t)r * ldc + col;
                    *(uint32_t*)(Ch + o) = pack_bf(h0, h1);
                    *(uint32_t*)(Cl + o) =
                        pack_bf(__float2bfloat16(v0 - __bfloat162float(h0)),
                                __float2bfloat16(v1 - __bfloat162float(h1)));
                } else {
                    s0 += v0; s1 += v1;
                }
            }
            if (sum_only) {
                atomicAdd(&colsum[col], s0);
                atomicAdd(&colsum[col + 1], s1);
            }
        }
    }
    if (sum_only) {
        __syncthreads();
        if (tid < 128) atomicAdd(&g_hsum[tid], colsum[tid]);
    }
}

// ---------------------------------------------------------------------------
// es2 (+ per-head global max)
// ---------------------------------------------------------------------------
__global__ void es2_kernel(int N, int H) {
    __shared__ float wt[CDIM * 10];
    __shared__ unsigned smax2[16];
    int tid = threadIdx.x;
    int TW = CDIM * 2 * H;
    for (int i = tid; i < TW; i += blockDim.x) wt[i] = g_fold2[i];
    if (tid < 16) smax2[tid] = 0u;
    __syncthreads();
    int warp = blockIdx.x * (blockDim.x >> 5) + (tid >> 5);
    int lane = tid & 31;
    bool valid = (warp < N);
    float4 hv = make_float4(0.f, 0.f, 0.f, 0.f);
    if (valid) hv = *(const float4*)(g_h1 + (size_t)warp * CDIM + lane * 4);
    float s[10];
#pragma unroll
    for (int o = 0; o < 10; o++) s[o] = 0.f;
    float hvv[4] = {hv.x, hv.y, hv.z, hv.w};
#pragma unroll
    for (int j = 0; j < 4; j++) {
        int c = lane * 4 + j;
        for (int o = 0; o < 2 * H; o++) s[o] += hvv[j] * wt[c * (2 * H) + o];
    }
    for (int o = 0; o < 2 * H; o++)
        for (int off = 16; off; off >>= 1) s[o] += __shfl_xor_sync(0xffffffffu, s[o], off);
    if (valid) {
        if (lane < H)          g_es2p[warp * 8 + lane] = s[lane];
        else if (lane < 2 * H) g_ed2p[warp * 8 + lane - H] = s[lane];
    }
    if (lane < 2 * H) atomicMax(&smax2[lane], fenc(valid ? s[lane] : -1e30f));
    __syncthreads();
    if (tid < 2 * H) atomicMax(&g_emax[8 + tid], smax2[tid]);
}

// ---------------------------------------------------------------------------
// Layer-2 aggregation (single gather pass; global upper-bound max)
// ---------------------------------------------------------------------------
__global__ void agg2_kernel(const float* __restrict__ feat, int N) {
    const int H = 5;
    int warp = (blockIdx.x * blockDim.x + threadIdx.x) >> 5;
    int lane = threadIdx.x & 31;
    if (warp >= N) return;
    int n   = warp;
    int r0  = g_rowptr[n];
    int deg = g_rowptr[n + 1] - r0;
    int tot = deg + 1;

    float edv[H], m[H];
    {
        float4 e4 = *(const float4*)(g_ed2p + n * 8);
        edv[0] = e4.x; edv[1] = e4.y; edv[2] = e4.z; edv[3] = e4.w;
        edv[4] = g_ed2p[n * 8 + 4];
    }
#pragma unroll
    for (int h = 0; h < H; h++) {
        float e = fdec(g_emax[8 + h]) + fdec(g_emax[13 + h]);
        m[h] = e > 0.f ? e : 0.2f * e;
    }

    float4 acc[H];
    float zp[H];
#pragma unroll
    for (int h = 0; h < H; h++) { acc[h] = make_float4(0.f, 0.f, 0.f, 0.f); zp[h] = 0.f; }

    for (int t = 0; t < tot; t += 32) {
        int i = t + lane;
        int src = n;
        float w[H];
        if (i < tot) {
            src = (i < deg) ? g_csrc[r0 + i] : n;
            float4 e4 = *(const float4*)(g_es2p + src * 8);
            float ev[H] = {e4.x, e4.y, e4.z, e4.w, g_es2p[src * 8 + 4]};
#pragma unroll
            for (int h = 0; h < H; h++) {
                float e = ev[h] + edv[h];
                e = e > 0.f ? e : 0.2f * e;
                w[h] = __expf(e - m[h]);
                zp[h] += w[h];
            }
        } else {
#pragma unroll
            for (int h = 0; h < H; h++) w[h] = 0.f;
        }
        int cnt = tot - t;
        if (cnt > 32) cnt = 32;
#pragma unroll 4
        for (int j = 0; j < cnt; j++) {
            int s = __shfl_sync(0xffffffffu, src, j);
            float wj[H];
#pragma unroll
            for (int h = 0; h < H; h++) wj[h] = __shfl_sync(0xffffffffu, w[h], j);
            float4 v = *(const float4*)(feat + (size_t)s * CDIM + lane * 4);
#pragma unroll
            for (int h = 0; h < H; h++) {
                acc[h].x += wj[h] * v.x; acc[h].y += wj[h] * v.y;
                acc[h].z += wj[h] * v.z; acc[h].w += wj[h] * v.w;
            }
        }
    }
#pragma unroll
    for (int h = 0; h < H; h++)
        for (int o = 16; o; o >>= 1) zp[h] += __shfl_xor_sync(0xffffffffu, zp[h], o);

#pragma unroll
    for (int h = 0; h < H; h++) {
        float iz = 1.f / zp[h];
        float ax = acc[h].x * iz, ay = acc[h].y * iz;
        float az = acc[h].z * iz, aw = acc[h].w * iz;
        __nv_bfloat16 hx = __float2bfloat16(ax);
        __nv_bfloat16 hy = __float2bfloat16(ay);
        __nv_bfloat16 hz = __float2bfloat16(az);
        __nv_bfloat16 hw = __float2bfloat16(aw);
        size_t o = (size_t)n * (H * CDIM) + h * CDIM + lane * 4;
        *(uint2*)(g_A2h + o) = make_uint2(pack_bf(hx, hy), pack_bf(hz, hw));
        *(uint2*)(g_A2l + o) = make_uint2(
            pack_bf(__float2bfloat16(ax - __bfloat162float(hx)),
                    __float2bfloat16(ay - __bfloat162float(hy))),
            pack_bf(__float2bfloat16(az - __bfloat162float(hz)),
                    __float2bfloat16(aw - __bfloat162float(hw))));
    }
}

// ---------------------------------------------------------------------------
// tails (R13 structure)
// ---------------------------------------------------------------------------
__global__ void tail0_kernel(const float* __restrict__ Wfc, const float* __restrict__ bfc,
                             const float* __restrict__ Whg, const float* __restrict__ bhg,
                             const float* __restrict__ Wv,  const float* __restrict__ bv,
                             const float* __restrict__ h_mat, const float* __restrict__ h_bias,
                             int N, int HOUT) {
    __shared__ float h[128];
    __shared__ float tm[256];
    __shared__ float hg[128];
    int tid = threadIdx.x;
    if (tid < 128) h[tid] = g_hsum[tid] / (float)N;
    __syncthreads();
    if (tid < 256) {
        float a = bfc[tid];
        for (int i = 0; i < 128; i++) a += h[i] * Wfc[i * 256 + tid];
        tm[tid] = a > 0.f ? a : 0.f;
    }
    __syncthreads();
    if (tid < 128) {
        float a = bhg[tid];
        for (int i = 0; i < 256; i++) a += tm[i] * Whg[i * 128 + tid];
        hg[tid] = a;
    }
    __syncthreads();
    if (tid < 384) {
        float a = bv[tid];
        for (int i = 0; i < 128; i++) a += hg[i] * Wv[i * 384 + tid];
        g_small[tid] = a > 0.f ? a : 0.f;
        float hs = 0.f;
        for (int hh = 0; hh < HOUT; hh++) hs += h_mat[hh * 384 + tid];
        g_small[384 + tid] = hs;
    }
    if (tid == 0) {
        float hb = 0.f;
        for (int i = 0; i < HOUT; i++) hb += h_bias[i];
        g_small[768] = hb;
    }
}

__global__ void tail1_kernel(int B) {
    __shared__ float red[128];
    int b = blockIdx.x, tid = threadIdx.x;  // 128 threads
    float part = 0.f;
    for (int mI = tid; mI < 384; mI += 128)
        part += g_small[384 + mI] * g_small[mI] * g_qrow[b * 384 + mI];
    red[tid] = part;
    __syncthreads();
    for (int o = 64; o; o >>= 1) {
        if (tid < o) red[tid] += red[tid + o];
        __syncthreads();
    }
    float att = red[0] + g_small[768];
    float l = 0.f;
#pragma unroll
    for (int j = 0; j < 3; j++) {
        int k = tid * 3 + j;
        l += g_small[k] * g_qrow[b * 384 + k];
    }
    float v = att * l;
    g_logits[b * 128 + tid] = v;
    atomicAdd(&g_bn1[tid], v);
    atomicAdd(&g_bn2[tid], v * v);
}

__global__ void tail2_kernel(const float* __restrict__ gamma,
                             const float* __restrict__ beta,
                             float* __restrict__ out, int B) {
    int idx = blockIdx.x * blockDim.x + threadIdx.x;
    if (idx >= B * 128) return;
    int c = idx & 127;
    float mu  = g_bn1[c] / (float)B;
    float var = g_bn2[c] / (float)B - mu * mu;
    float v = g_logits[idx];
    out[idx] = (v - mu) * rsqrtf(var + 1e-5f) * gamma[c] + beta[c];
}

// ---------------------------------------------------------------------------
// launch
// ---------------------------------------------------------------------------
extern "C" void kernel_launch(void* const* d_in, const int* in_sizes, int n_in,
                              void* d_out, int out_size) {
    const float* cell = (const float*)d_in[0];
    const float* Wd   = (const float*)d_in[1];
    const float* bd   = (const float*)d_in[2];
    const float* W1   = (const float*)d_in[3];
    const float* a1s  = (const float*)d_in[4];
    const float* a1d  = (const float*)d_in[5];
    const float* b1   = (const float*)d_in[6];
    const float* Wl1  = (const float*)d_in[7];
    const float* bl1  = (const float*)d_in[8];
    const float* W2   = (const float*)d_in[9];
    const float* a2s  = (const float*)d_in[10];
    const float* a2d  = (const float*)d_in[11];
    const float* b2   = (const float*)d_in[12];
    const float* Wl2  = (const float*)d_in[13];
    const float* bl2  = (const float*)d_in[14];
    const float* Wfc  = (const float*)d_in[15];
    const float* bfc  = (const float*)d_in[16];
    const float* Whg  = (const float*)d_in[17];
    const float* bhg  = (const float*)d_in[18];
    const float* Wc   = (const float*)d_in[19];
    const float* bc   = (const float*)d_in[20];
    const float* Wv   = (const float*)d_in[21];
    const float* bv   = (const float*)d_in[22];
    const float* Wq   = (const float*)d_in[23];
    const float* bq   = (const float*)d_in[24];
    const float* h_mat  = (const float*)d_in[25];
    const float* h_bias = (const float*)d_in[26];
    const float* gamma  = (const float*)d_in[27];
    const float* beta   = (const float*)d_in[28];
    const int*   trip   = (const int*)d_in[29];
    const int*   ei     = (const int*)d_in[30];

    int N  = in_sizes[29] / 4;
    int E  = in_sizes[30] / 2;
    int CF = in_sizes[19] / 128;
    int B  = in_sizes[0] / CF;
    int H1 = in_sizes[4] / 128;   // 4
    int H2 = in_sizes[10] / 128;  // 5
    int HOUT = in_sizes[26];
    if (N > NMAX) N = NMAX;
    if (E > EMAX) E = EMAX;
    float* out = (float*)d_out;

    void *ph1;
    void *pA2h, *pA2l, *pA3h, *pA3l;
    void *pb1h, *pb1l, *pb2h, *pb2l, *pb3h, *pb3l;
    cudaGetSymbolAddress(&ph1,  g_h1);
    cudaGetSymbolAddress(&pA2h, g_A2h);
    cudaGetSymbolAddress(&pA2l, g_A2l);
    cudaGetSymbolAddress(&pA3h, g_A3h);
    cudaGetSymbolAddress(&pA3l, g_A3l);
    cudaGetSymbolAddress(&pb1h, g_bt1h);
    cudaGetSymbolAddress(&pb1l, g_bt1l);
    cudaGetSymbolAddress(&pb2h, g_bt2h);
    cudaGetSymbolAddress(&pb2l, g_bt2l);
    cudaGetSymbolAddress(&pb3h, g_bt3h);
    cudaGetSymbolAddress(&pb3l, g_bt3l);

    cudaFuncSetAttribute(tgemm,    cudaFuncAttributeMaxDynamicSharedMemorySize, 49152);
    cudaFuncSetAttribute(tgemm_r4, cudaFuncAttributeMaxDynamicSharedMemorySize, 49152);

    int M1 = H1 * CDIM;  // 512
    int M2 = H2 * CDIM;  // 640
    int mt = (N + 63) / 64;

    // ---- prep ----
    int s0 = (N + 255) / 256;
    int s1 = (128 * M1 + 255) / 256;
    int s2 = (128 * 128 * H2 + 255) / 256;
    int s3 = (128 * M2 + 255) / 256;
    int s4 = (M1 + 255) / 256;
    int s5 = (CDIM * 2 * H2 + 255) / 256;
    prep_kernel<<<s0 + s1 + s2 + s3 + s4 + s5, 256>>>(Wl1, W2, Wl2, Wd, bd, W1,
                                                      a2s, a2d,
                                                      N, M1, M2, H2, s0, s1, s2, s3, s4);

    // ---- combined: count + es1(+max) + q-precompute ----
    int c0 = (E / 2 + 255) / 256;
    int c1 = (N + 255) / 256;
    cnt_es1_q_kernel<<<c0 + c1 + B, 256>>>(ei, E, trip, a1s, a1d, N, M1,
                                           cell, Wc, bc, Wq, bq, CF, c0, c1);

    scan_kernel<<<1, 1024>>>(N);
    fill_kernel<<<(E / 2 + 255) / 256, 256>>>(ei, E);

    // ---- GAT layer 1 ----
    agg_rank4_kernel<<<(N * 32 + 255) / 256, 256>>>(trip, N);
    tgemm_r4<<<dim3(1, mt, 1), 256, 49152>>>(
        b1, (const __nv_bfloat16*)pb1h, (const __nv_bfloat16*)pb1l,
        (float*)ph1, N, bl1);

    // ---- GAT layer 2 ----
    es2_kernel<<<(N + 7) / 8, 256>>>(N, H2);
    agg2_kernel<<<(N * 32 + 255) / 256, 256>>>((const float*)ph1, N);
    tgemm<<<dim3(1, mt, H2), 256, 49152>>>(
        (const __nv_bfloat16*)pA2h, (const __nv_bfloat16*)pA2l, M2, 128,
        (const __nv_bfloat16*)pb2h, (const __nv_bfloat16*)pb2l, 128 * 128,
        nullptr, (__nv_bfloat16*)pA3h, (__nv_bfloat16*)pA3l, M2, 128,
        N, 128, b2, 128, 1);
    tgemm<<<dim3(1, mt, 1), 256, 49152>>>(
        (const __nv_bfloat16*)pA3h, (const __nv_bfloat16*)pA3l, M2, 0,
        (const __nv_bfloat16*)pb3h, (const __nv_bfloat16*)pb3l, 0,
        nullptr, nullptr, nullptr, CDIM, 0, N, M2, bl2, 0, 0);

    // ---- tail (R13 structure) ----
    tail0_kernel<<<1, 384>>>(Wfc, bfc, Whg, bhg, Wv, bv, h_mat, h_bias, N, HOUT);
    tail1_kernel<<<B, 128>>>(B);
    tail2_kernel<<<(B * 128 + 255) / 256, 256>>>(gamma, beta, out, B);
}